// round 1
// baseline (speedup 1.0000x reference)
#include <cuda_runtime.h>

#define Bq 2
#define Nq 2048
#define Hq 16
#define DHq 64
#define Dq 1024
#define HDq (Hq * DHq)   // 1024
#define Mq (Bq * Nq)     // 4096

// Scratch: Q, K, V, attention-out, each [B, N, H, DH] fp32 = 16 MB
__device__ float g_q[Bq * Nq * HDq];
__device__ float g_k[Bq * Nq * HDq];
__device__ float g_v[Bq * Nq * HDq];
__device__ float g_ao[Bq * Nq * HDq];

// ---------------------------------------------------------------------------
// Generic 128x128 tile SGEMM core: C[4096,1024] = A[4096,1024] @ W[1024,1024]
// BM=128, BN=128, BK=8, TM=TN=8, 256 threads.
// ---------------------------------------------------------------------------
__device__ __forceinline__ void gemm_tile(const float* __restrict__ A,
                                          const float* __restrict__ W,
                                          float* __restrict__ C,
                                          const float* __restrict__ bias,
                                          int rowBlk, int colBlk,
                                          float* As, float* Bs)
{
    const int tid  = threadIdx.x;
    const int aRow = tid >> 1, aCol = (tid & 1) * 4;   // A tile 128x8
    const int bRow = tid >> 5, bCol = (tid & 31) * 4;  // W tile 8x128
    const int tr   = tid >> 4, tc = tid & 15;          // 16x16 compute grid

    const float* Ap = A + (size_t)(rowBlk * 128) * Dq;
    const float* Wp = W + colBlk * 128;

    float acc[8][8] = {};

    for (int k0 = 0; k0 < Dq; k0 += 8) {
        float4 a4 = *(const float4*)(Ap + (size_t)aRow * Dq + k0 + aCol);
        As[(aCol + 0) * 128 + aRow] = a4.x;
        As[(aCol + 1) * 128 + aRow] = a4.y;
        As[(aCol + 2) * 128 + aRow] = a4.z;
        As[(aCol + 3) * 128 + aRow] = a4.w;
        *(float4*)(Bs + bRow * 128 + bCol) =
            *(const float4*)(Wp + (size_t)(k0 + bRow) * Dq + bCol);
        __syncthreads();
#pragma unroll
        for (int k = 0; k < 8; k++) {
            float4 a0 = *(float4*)(As + k * 128 + tr * 8);
            float4 a1 = *(float4*)(As + k * 128 + tr * 8 + 4);
            float4 b0 = *(float4*)(Bs + k * 128 + tc * 8);
            float4 b1 = *(float4*)(Bs + k * 128 + tc * 8 + 4);
            float rm[8] = {a0.x, a0.y, a0.z, a0.w, a1.x, a1.y, a1.z, a1.w};
            float rn[8] = {b0.x, b0.y, b0.z, b0.w, b1.x, b1.y, b1.z, b1.w};
#pragma unroll
            for (int i = 0; i < 8; i++)
#pragma unroll
                for (int j = 0; j < 8; j++)
                    acc[i][j] = fmaf(rm[i], rn[j], acc[i][j]);
        }
        __syncthreads();
    }

#pragma unroll
    for (int i = 0; i < 8; i++) {
        size_t row = (size_t)rowBlk * 128 + tr * 8 + i;
#pragma unroll
        for (int j = 0; j < 8; j += 4) {
            int col = colBlk * 128 + tc * 8 + j;
            float4 v = make_float4(acc[i][j], acc[i][j + 1], acc[i][j + 2], acc[i][j + 3]);
            if (bias) {
                v.x += bias[col];
                v.y += bias[col + 1];
                v.z += bias[col + 2];
                v.w += bias[col + 3];
            }
            *(float4*)(C + row * Dq + col) = v;
        }
    }
}

// Fused QKV projection: 24 column-blocks (8 per weight) x 32 row-blocks
__global__ __launch_bounds__(256) void qkv_gemm(const float* __restrict__ x,
                                                const float* __restrict__ Wq,
                                                const float* __restrict__ Wk,
                                                const float* __restrict__ Wv)
{
    __shared__ float As[8 * 128], Bs[8 * 128];
    int w = blockIdx.x >> 3, colBlk = blockIdx.x & 7;
    const float* W = (w == 0) ? Wq : (w == 1) ? Wk : Wv;
    float* C       = (w == 0) ? g_q : (w == 1) ? g_k : g_v;
    gemm_tile(x, W, C, nullptr, blockIdx.y, colBlk, As, Bs);
}

// Output projection with bias
__global__ __launch_bounds__(256) void out_proj(const float* __restrict__ Wo,
                                                const float* __restrict__ bo,
                                                float* __restrict__ out)
{
    __shared__ float As[8 * 128], Bs[8 * 128];
    gemm_tile(g_ao, Wo, out, bo, blockIdx.y, blockIdx.x, As, Bs);
}

// ---------------------------------------------------------------------------
// Flash attention with ALiBi + causal mask.
// BR=128 queries / block, BC=64 keys / tile, 128 threads.
// smem: Qs[d][i] 64x128, Ks[d][j] 64x64, Vs[j][d] 64x64, Ps[j][i] 64x128, rowf[128]
// ---------------------------------------------------------------------------
#define FL_SMEM ((64 * 128 + 64 * 64 + 64 * 64 + 64 * 128 + 128) * 4)

__global__ __launch_bounds__(128) void flash_alibi()
{
    extern __shared__ float sm[];
    float* Qs   = sm;               // 64 x 128   (d-major, i inner)
    float* Ks   = Qs + 64 * 128;    // 64 x 64    (d-major, j inner)
    float* Vs   = Ks + 64 * 64;     // 64 x 64    (j-major, d inner)
    float* Ps   = Vs + 64 * 64;     // 64 x 128   (j-major, i inner)
    float* rowf = Ps + 64 * 128;    // 128

    const int tid = threadIdx.x;
    const int i0  = blockIdx.x * 128;
    const int h   = blockIdx.y;
    const int b   = blockIdx.z;
    const float slope = exp2f(-0.5f * (float)(h + 1));

    // Load Q tile (transposed into Qs[d][i])
    const float* Qg = g_q + ((size_t)(b * Nq + i0) * Hq + h) * DHq;
    for (int idx = tid; idx < 128 * 16; idx += 128) {
        int i = idx >> 4, dv = (idx & 15) * 4;
        float4 v = *(const float4*)(Qg + (size_t)i * HDq + dv);
        Qs[(dv + 0) * 128 + i] = v.x;
        Qs[(dv + 1) * 128 + i] = v.y;
        Qs[(dv + 2) * 128 + i] = v.z;
        Qs[(dv + 3) * 128 + i] = v.w;
    }

    const int tr = tid >> 3, tc = tid & 7;   // 16 x 8 compute grid, 8x8 microtile
    float acc_o[8][8] = {};
    float m_i = -1e30f, l_i = 0.f;

    const int nj = (i0 + 128) / 64;          // causal: only tiles with j0 <= i_max
    for (int jt = 0; jt < nj; jt++) {
        const int j0 = jt * 64;
        __syncthreads();   // protect prior-iteration Ps/Vs reads before overwrite
        for (int idx = tid; idx < 64 * 16; idx += 128) {
            int j = idx >> 4, dv = (idx & 15) * 4;
            size_t base = ((size_t)(b * Nq + j0 + j) * Hq + h) * DHq + dv;
            float4 kv = *(const float4*)(g_k + base);
            Ks[(dv + 0) * 64 + j] = kv.x;
            Ks[(dv + 1) * 64 + j] = kv.y;
            Ks[(dv + 2) * 64 + j] = kv.z;
            Ks[(dv + 3) * 64 + j] = kv.w;
            *(float4*)(Vs + j * 64 + dv) = *(const float4*)(g_v + base);
        }
        __syncthreads();

        // S = Q @ K^T (microtiled)
        float acc[8][8] = {};
#pragma unroll 8
        for (int d = 0; d < 64; d++) {
            float4 a0 = *(float4*)(Qs + d * 128 + tr * 8);
            float4 a1 = *(float4*)(Qs + d * 128 + tr * 8 + 4);
            float4 b0 = *(float4*)(Ks + d * 64 + tc * 8);
            float4 b1 = *(float4*)(Ks + d * 64 + tc * 8 + 4);
            float rm[8] = {a0.x, a0.y, a0.z, a0.w, a1.x, a1.y, a1.z, a1.w};
            float rn[8] = {b0.x, b0.y, b0.z, b0.w, b1.x, b1.y, b1.z, b1.w};
#pragma unroll
            for (int ii = 0; ii < 8; ii++)
#pragma unroll
                for (int jj = 0; jj < 8; jj++)
                    acc[ii][jj] = fmaf(rm[ii], rn[jj], acc[ii][jj]);
        }

        // scale + ALiBi + causal mask, write transposed to Ps[j][i]
#pragma unroll
        for (int ii = 0; ii < 8; ii++) {
            int ig = i0 + tr * 8 + ii;
#pragma unroll
            for (int jj = 0; jj < 8; jj++) {
                int jg = j0 + tc * 8 + jj;
                float v = fmaf(acc[ii][jj], 0.125f, slope * (float)(ig - jg));
                if (jg > ig) v = -1e30f;
                Ps[(tc * 8 + jj) * 128 + (tr * 8 + ii)] = v;
            }
        }
        __syncthreads();

        // Online softmax: thread tid owns query row tid
        {
            float mt = -1e30f;
#pragma unroll 8
            for (int c = 0; c < 64; c++) mt = fmaxf(mt, Ps[c * 128 + tid]);
            float m_new = fmaxf(m_i, mt);
            float f = __expf(fmaxf(m_i - m_new, -80.f));
            float s = 0.f;
#pragma unroll 8
            for (int c = 0; c < 64; c++) {
                float p = __expf(fmaxf(Ps[c * 128 + tid] - m_new, -80.f));
                Ps[c * 128 + tid] = p;
                s += p;
            }
            l_i = l_i * f + s;
            m_i = m_new;
            rowf[tid] = f;
        }
        __syncthreads();

        // Rescale O, then O += P @ V (microtiled)
        float fr[8];
#pragma unroll
        for (int ii = 0; ii < 8; ii++) fr[ii] = rowf[tr * 8 + ii];
#pragma unroll
        for (int ii = 0; ii < 8; ii++)
#pragma unroll
            for (int jj = 0; jj < 8; jj++) acc_o[ii][jj] *= fr[ii];

#pragma unroll 8
        for (int c = 0; c < 64; c++) {
            float4 a0 = *(float4*)(Ps + c * 128 + tr * 8);
            float4 a1 = *(float4*)(Ps + c * 128 + tr * 8 + 4);
            float4 b0 = *(float4*)(Vs + c * 64 + tc * 8);
            float4 b1 = *(float4*)(Vs + c * 64 + tc * 8 + 4);
            float rm[8] = {a0.x, a0.y, a0.z, a0.w, a1.x, a1.y, a1.z, a1.w};
            float rn[8] = {b0.x, b0.y, b0.z, b0.w, b1.x, b1.y, b1.z, b1.w};
#pragma unroll
            for (int ii = 0; ii < 8; ii++)
#pragma unroll
                for (int jj = 0; jj < 8; jj++)
                    acc_o[ii][jj] = fmaf(rm[ii], rn[jj], acc_o[ii][jj]);
        }
    }

    // Normalize and write out
    __syncthreads();
    rowf[tid] = 1.f / l_i;
    __syncthreads();
    float fr[8];
#pragma unroll
    for (int ii = 0; ii < 8; ii++) fr[ii] = rowf[tr * 8 + ii];
    float* Og = g_ao + ((size_t)(b * Nq + i0) * Hq + h) * DHq;
#pragma unroll
    for (int ii = 0; ii < 8; ii++) {
        int r = tr * 8 + ii;
#pragma unroll
        for (int jj = 0; jj < 8; jj += 4) {
            float4 v = make_float4(acc_o[ii][jj] * fr[ii], acc_o[ii][jj + 1] * fr[ii],
                                   acc_o[ii][jj + 2] * fr[ii], acc_o[ii][jj + 3] * fr[ii]);
            *(float4*)(Og + (size_t)r * HDq + tc * 8 + jj) = v;
        }
    }
}

// ---------------------------------------------------------------------------
extern "C" void kernel_launch(void* const* d_in, const int* in_sizes, int n_in,
                              void* d_out, int out_size)
{
    (void)in_sizes; (void)n_in; (void)out_size;
    const float* x  = (const float*)d_in[0];
    const float* Wq = (const float*)d_in[1];
    const float* Wk = (const float*)d_in[2];
    const float* Wv = (const float*)d_in[3];
    const float* Wo = (const float*)d_in[4];
    const float* bo = (const float*)d_in[5];
    float* out = (float*)d_out;

    cudaFuncSetAttribute(flash_alibi, cudaFuncAttributeMaxDynamicSharedMemorySize, FL_SMEM);

    qkv_gemm<<<dim3(24, 32), 256>>>(x, Wq, Wk, Wv);
    flash_alibi<<<dim3(16, 16, 2), 128, FL_SMEM>>>();
    out_proj<<<dim3(8, 32), 256>>>(Wo, bo, out);
}

// round 2
// speedup vs baseline: 1.0896x; 1.0896x over previous
#include <cuda_runtime.h>

#define Bq 2
#define Nq 2048
#define Hq 16
#define DHq 64
#define Dq 1024
#define HDq (Hq * DHq)   // 1024
#define Mq (Bq * Nq)     // 4096

// Scratch: Q, K, V, attention-out, each [B, N, H, DH] fp32 = 16 MB
__device__ float g_q[Bq * Nq * HDq];
__device__ float g_k[Bq * Nq * HDq];
__device__ float g_v[Bq * Nq * HDq];
__device__ float g_ao[Bq * Nq * HDq];

// ---------------------------------------------------------------------------
// 3xTF32 split helpers + mma.sync wrapper
// ---------------------------------------------------------------------------
__device__ __forceinline__ void split_tf32(float x, float& hi, float& lo)
{
    unsigned h;
    asm("cvt.rna.tf32.f32 %0, %1;" : "=r"(h) : "f"(x));
    hi = __uint_as_float(h);
    float r = x - hi;
    unsigned l;
    asm("cvt.rna.tf32.f32 %0, %1;" : "=r"(l) : "f"(r));
    lo = __uint_as_float(l);
}

#define MMA_TF32(d, a, b)                                                     \
    asm volatile("mma.sync.aligned.m16n8k8.row.col.f32.tf32.tf32.f32 "        \
                 "{%0,%1,%2,%3}, {%4,%5,%6,%7}, {%8,%9}, {%0,%1,%2,%3};"      \
                 : "+f"(d[0]), "+f"(d[1]), "+f"(d[2]), "+f"(d[3])             \
                 : "r"(a[0]), "r"(a[1]), "r"(a[2]), "r"(a[3]),                \
                   "r"(b[0]), "r"(b[1]))

// ---------------------------------------------------------------------------
// 3xTF32 tensor-core GEMM tile: C[128,128] += A[128,1024] @ W[1024,128]
// BM=128 BN=128 BK=32, 8 warps (warp tile 32x64), mma m16n8k8.
// smem strides chosen for conflict-free fragment LDS:
//   A stored [m][k] stride 36  (banks: 4m+k bijective over a frag-load)
//   W stored [k][n] stride 136 (banks: 8k+n bijective over a frag-load)
// ---------------------------------------------------------------------------
#define ASTR 36
#define WSTR 136
#define GEMM_SMEM ((128 * ASTR * 2 + 32 * WSTR * 2) * 4)   // 71680 B

__device__ __forceinline__ void gemm3x_tile(const float* __restrict__ A,
                                            const float* __restrict__ W,
                                            float* __restrict__ C,
                                            const float* __restrict__ bias,
                                            int rowBlk, int colBlk)
{
    extern __shared__ float sm[];
    float* Ah = sm;                       // [128][36]
    float* Al = Ah + 128 * ASTR;
    float* Wh = Al + 128 * ASTR;          // [32][136]
    float* Wl = Wh + 32 * WSTR;

    const int tid  = threadIdx.x;
    const int wid  = tid >> 5, lane = tid & 31;
    const int g    = lane >> 2, t = lane & 3;
    const int wm   = (wid & 3) * 32;      // warp row offset
    const int wn   = (wid >> 2) * 64;     // warp col offset

    const float* Ap = A + (size_t)(rowBlk * 128) * Dq;
    const float* Wp = W + colBlk * 128;

    // global-load assignments
    const int ar = tid >> 1, ac = (tid & 1) * 16;   // A: 128 rows x 32 cols
    const int wr = tid >> 3, wc = (tid & 7) * 16;   // W: 32 rows x 128 cols

    float acc[2][8][4] = {};

    for (int k0 = 0; k0 < Dq; k0 += 32) {
        __syncthreads();
#pragma unroll
        for (int i = 0; i < 4; i++) {
            float4 v = *(const float4*)(Ap + (size_t)ar * Dq + k0 + ac + i * 4);
            float h, l;
            split_tf32(v.x, h, l); Ah[ar * ASTR + ac + i * 4 + 0] = h; Al[ar * ASTR + ac + i * 4 + 0] = l;
            split_tf32(v.y, h, l); Ah[ar * ASTR + ac + i * 4 + 1] = h; Al[ar * ASTR + ac + i * 4 + 1] = l;
            split_tf32(v.z, h, l); Ah[ar * ASTR + ac + i * 4 + 2] = h; Al[ar * ASTR + ac + i * 4 + 2] = l;
            split_tf32(v.w, h, l); Ah[ar * ASTR + ac + i * 4 + 3] = h; Al[ar * ASTR + ac + i * 4 + 3] = l;
        }
#pragma unroll
        for (int i = 0; i < 4; i++) {
            float4 v = *(const float4*)(Wp + (size_t)(k0 + wr) * Dq + wc + i * 4);
            float h, l;
            split_tf32(v.x, h, l); Wh[wr * WSTR + wc + i * 4 + 0] = h; Wl[wr * WSTR + wc + i * 4 + 0] = l;
            split_tf32(v.y, h, l); Wh[wr * WSTR + wc + i * 4 + 1] = h; Wl[wr * WSTR + wc + i * 4 + 1] = l;
            split_tf32(v.z, h, l); Wh[wr * WSTR + wc + i * 4 + 2] = h; Wl[wr * WSTR + wc + i * 4 + 2] = l;
            split_tf32(v.w, h, l); Wh[wr * WSTR + wc + i * 4 + 3] = h; Wl[wr * WSTR + wc + i * 4 + 3] = l;
        }
        __syncthreads();

#pragma unroll
        for (int kk = 0; kk < 32; kk += 8) {
            unsigned ah[2][4], al[2][4];
#pragma unroll
            for (int mt = 0; mt < 2; mt++) {
                int r0 = wm + mt * 16 + g;
                ah[mt][0] = __float_as_uint(Ah[(r0    ) * ASTR + kk + t    ]);
                ah[mt][1] = __float_as_uint(Ah[(r0 + 8) * ASTR + kk + t    ]);
                ah[mt][2] = __float_as_uint(Ah[(r0    ) * ASTR + kk + t + 4]);
                ah[mt][3] = __float_as_uint(Ah[(r0 + 8) * ASTR + kk + t + 4]);
                al[mt][0] = __float_as_uint(Al[(r0    ) * ASTR + kk + t    ]);
                al[mt][1] = __float_as_uint(Al[(r0 + 8) * ASTR + kk + t    ]);
                al[mt][2] = __float_as_uint(Al[(r0    ) * ASTR + kk + t + 4]);
                al[mt][3] = __float_as_uint(Al[(r0 + 8) * ASTR + kk + t + 4]);
            }
            unsigned bh[8][2], bl[8][2];
#pragma unroll
            for (int nt = 0; nt < 8; nt++) {
                int c = wn + nt * 8 + g;
                bh[nt][0] = __float_as_uint(Wh[(kk + t    ) * WSTR + c]);
                bh[nt][1] = __float_as_uint(Wh[(kk + t + 4) * WSTR + c]);
                bl[nt][0] = __float_as_uint(Wl[(kk + t    ) * WSTR + c]);
                bl[nt][1] = __float_as_uint(Wl[(kk + t + 4) * WSTR + c]);
            }
#pragma unroll
            for (int mt = 0; mt < 2; mt++)
#pragma unroll
                for (int nt = 0; nt < 8; nt++) {
                    MMA_TF32(acc[mt][nt], ah[mt], bh[nt]);
                    MMA_TF32(acc[mt][nt], al[mt], bh[nt]);
                    MMA_TF32(acc[mt][nt], ah[mt], bl[nt]);
                }
        }
    }

    // epilogue
#pragma unroll
    for (int mt = 0; mt < 2; mt++) {
        int r0 = rowBlk * 128 + wm + mt * 16 + g;
#pragma unroll
        for (int nt = 0; nt < 8; nt++) {
            int c = colBlk * 128 + wn + nt * 8 + 2 * t;
            float b0 = 0.f, b1 = 0.f;
            if (bias) { b0 = bias[c]; b1 = bias[c + 1]; }
            *(float2*)(C + (size_t)r0 * Dq + c) =
                make_float2(acc[mt][nt][0] + b0, acc[mt][nt][1] + b1);
            *(float2*)(C + (size_t)(r0 + 8) * Dq + c) =
                make_float2(acc[mt][nt][2] + b0, acc[mt][nt][3] + b1);
        }
    }
}

__global__ __launch_bounds__(256) void qkv_gemm(const float* __restrict__ x,
                                                const float* __restrict__ Wq,
                                                const float* __restrict__ Wk,
                                                const float* __restrict__ Wv)
{
    int w = blockIdx.x >> 3, colBlk = blockIdx.x & 7;
    const float* W = (w == 0) ? Wq : (w == 1) ? Wk : Wv;
    float* C       = (w == 0) ? g_q : (w == 1) ? g_k : g_v;
    gemm3x_tile(x, W, C, nullptr, blockIdx.y, colBlk);
}

__global__ __launch_bounds__(256) void out_proj(const float* __restrict__ Wo,
                                                const float* __restrict__ bo,
                                                float* __restrict__ out)
{
    gemm3x_tile(g_ao, Wo, out, bo, blockIdx.y, blockIdx.x);
}

// ---------------------------------------------------------------------------
// Flash attention with ALiBi + causal mask (fp32 SIMT, unchanged from R0).
// BR=128 queries / block, BC=64 keys / tile, 128 threads.
// ---------------------------------------------------------------------------
#define FL_SMEM ((64 * 128 + 64 * 64 + 64 * 64 + 64 * 128 + 128) * 4)

__global__ __launch_bounds__(128) void flash_alibi()
{
    extern __shared__ float sm[];
    float* Qs   = sm;               // 64 x 128   (d-major, i inner)
    float* Ks   = Qs + 64 * 128;    // 64 x 64    (d-major, j inner)
    float* Vs   = Ks + 64 * 64;     // 64 x 64    (j-major, d inner)
    float* Ps   = Vs + 64 * 64;     // 64 x 128   (j-major, i inner)
    float* rowf = Ps + 64 * 128;    // 128

    const int tid = threadIdx.x;
    const int i0  = blockIdx.x * 128;
    const int h   = blockIdx.y;
    const int b   = blockIdx.z;
    const float slope = exp2f(-0.5f * (float)(h + 1));

    const float* Qg = g_q + ((size_t)(b * Nq + i0) * Hq + h) * DHq;
    for (int idx = tid; idx < 128 * 16; idx += 128) {
        int i = idx >> 4, dv = (idx & 15) * 4;
        float4 v = *(const float4*)(Qg + (size_t)i * HDq + dv);
        Qs[(dv + 0) * 128 + i] = v.x;
        Qs[(dv + 1) * 128 + i] = v.y;
        Qs[(dv + 2) * 128 + i] = v.z;
        Qs[(dv + 3) * 128 + i] = v.w;
    }

    const int tr = tid >> 3, tc = tid & 7;
    float acc_o[8][8] = {};
    float m_i = -1e30f, l_i = 0.f;

    const int nj = (i0 + 128) / 64;
    for (int jt = 0; jt < nj; jt++) {
        const int j0 = jt * 64;
        __syncthreads();
        for (int idx = tid; idx < 64 * 16; idx += 128) {
            int j = idx >> 4, dv = (idx & 15) * 4;
            size_t base = ((size_t)(b * Nq + j0 + j) * Hq + h) * DHq + dv;
            float4 kv = *(const float4*)(g_k + base);
            Ks[(dv + 0) * 64 + j] = kv.x;
            Ks[(dv + 1) * 64 + j] = kv.y;
            Ks[(dv + 2) * 64 + j] = kv.z;
            Ks[(dv + 3) * 64 + j] = kv.w;
            *(float4*)(Vs + j * 64 + dv) = *(const float4*)(g_v + base);
        }
        __syncthreads();

        float acc[8][8] = {};
#pragma unroll 8
        for (int d = 0; d < 64; d++) {
            float4 a0 = *(float4*)(Qs + d * 128 + tr * 8);
            float4 a1 = *(float4*)(Qs + d * 128 + tr * 8 + 4);
            float4 b0 = *(float4*)(Ks + d * 64 + tc * 8);
            float4 b1 = *(float4*)(Ks + d * 64 + tc * 8 + 4);
            float rm[8] = {a0.x, a0.y, a0.z, a0.w, a1.x, a1.y, a1.z, a1.w};
            float rn[8] = {b0.x, b0.y, b0.z, b0.w, b1.x, b1.y, b1.z, b1.w};
#pragma unroll
            for (int ii = 0; ii < 8; ii++)
#pragma unroll
                for (int jj = 0; jj < 8; jj++)
                    acc[ii][jj] = fmaf(rm[ii], rn[jj], acc[ii][jj]);
        }

#pragma unroll
        for (int ii = 0; ii < 8; ii++) {
            int ig = i0 + tr * 8 + ii;
#pragma unroll
            for (int jj = 0; jj < 8; jj++) {
                int jg = j0 + tc * 8 + jj;
                float v = fmaf(acc[ii][jj], 0.125f, slope * (float)(ig - jg));
                if (jg > ig) v = -1e30f;
                Ps[(tc * 8 + jj) * 128 + (tr * 8 + ii)] = v;
            }
        }
        __syncthreads();

        {
            float mt = -1e30f;
#pragma unroll 8
            for (int c = 0; c < 64; c++) mt = fmaxf(mt, Ps[c * 128 + tid]);
            float m_new = fmaxf(m_i, mt);
            float f = __expf(fmaxf(m_i - m_new, -80.f));
            float s = 0.f;
#pragma unroll 8
            for (int c = 0; c < 64; c++) {
                float p = __expf(fmaxf(Ps[c * 128 + tid] - m_new, -80.f));
                Ps[c * 128 + tid] = p;
                s += p;
            }
            l_i = l_i * f + s;
            m_i = m_new;
            rowf[tid] = f;
        }
        __syncthreads();

        float fr[8];
#pragma unroll
        for (int ii = 0; ii < 8; ii++) fr[ii] = rowf[tr * 8 + ii];
#pragma unroll
        for (int ii = 0; ii < 8; ii++)
#pragma unroll
            for (int jj = 0; jj < 8; jj++) acc_o[ii][jj] *= fr[ii];

#pragma unroll 8
        for (int c = 0; c < 64; c++) {
            float4 a0 = *(float4*)(Ps + c * 128 + tr * 8);
            float4 a1 = *(float4*)(Ps + c * 128 + tr * 8 + 4);
            float4 b0 = *(float4*)(Vs + c * 64 + tc * 8);
            float4 b1 = *(float4*)(Vs + c * 64 + tc * 8 + 4);
            float rm[8] = {a0.x, a0.y, a0.z, a0.w, a1.x, a1.y, a1.z, a1.w};
            float rn[8] = {b0.x, b0.y, b0.z, b0.w, b1.x, b1.y, b1.z, b1.w};
#pragma unroll
            for (int ii = 0; ii < 8; ii++)
#pragma unroll
                for (int jj = 0; jj < 8; jj++)
                    acc_o[ii][jj] = fmaf(rm[ii], rn[jj], acc_o[ii][jj]);
        }
    }

    __syncthreads();
    rowf[tid] = 1.f / l_i;
    __syncthreads();
    float fr[8];
#pragma unroll
    for (int ii = 0; ii < 8; ii++) fr[ii] = rowf[tr * 8 + ii];
    float* Og = g_ao + ((size_t)(b * Nq + i0) * Hq + h) * DHq;
#pragma unroll
    for (int ii = 0; ii < 8; ii++) {
        int r = tr * 8 + ii;
#pragma unroll
        for (int jj = 0; jj < 8; jj += 4) {
            float4 v = make_float4(acc_o[ii][jj] * fr[ii], acc_o[ii][jj + 1] * fr[ii],
                                   acc_o[ii][jj + 2] * fr[ii], acc_o[ii][jj + 3] * fr[ii]);
            *(float4*)(Og + (size_t)r * HDq + tc * 8 + jj) = v;
        }
    }
}

// ---------------------------------------------------------------------------
extern "C" void kernel_launch(void* const* d_in, const int* in_sizes, int n_in,
                              void* d_out, int out_size)
{
    (void)in_sizes; (void)n_in; (void)out_size;
    const float* x  = (const float*)d_in[0];
    const float* Wq = (const float*)d_in[1];
    const float* Wk = (const float*)d_in[2];
    const float* Wv = (const float*)d_in[3];
    const float* Wo = (const float*)d_in[4];
    const float* bo = (const float*)d_in[5];
    float* out = (float*)d_out;

    cudaFuncSetAttribute(qkv_gemm,  cudaFuncAttributeMaxDynamicSharedMemorySize, GEMM_SMEM);
    cudaFuncSetAttribute(out_proj,  cudaFuncAttributeMaxDynamicSharedMemorySize, GEMM_SMEM);
    cudaFuncSetAttribute(flash_alibi, cudaFuncAttributeMaxDynamicSharedMemorySize, FL_SMEM);

    qkv_gemm<<<dim3(24, 32), 256, GEMM_SMEM>>>(x, Wq, Wk, Wv);
    flash_alibi<<<dim3(16, 16, 2), 128, FL_SMEM>>>();
    out_proj<<<dim3(8, 32), 256, GEMM_SMEM>>>(Wo, bo, out);
}

// round 4
// speedup vs baseline: 1.3791x; 1.2656x over previous
#include <cuda_runtime.h>

#define Bq 2
#define Nq 2048
#define Hq 16
#define DHq 64
#define Dq 1024
#define HDq (Hq * DHq)   // 1024
#define Mq (Bq * Nq)     // 4096

__device__ float g_q[Bq * Nq * HDq];
__device__ float g_k[Bq * Nq * HDq];
__device__ float g_v[Bq * Nq * HDq];
__device__ float g_ao[Bq * Nq * HDq];

// ---------------------------------------------------------------------------
// 3xTF32 helpers
// ---------------------------------------------------------------------------
__device__ __forceinline__ void split_tf32(float x, float& hi, float& lo)
{
    unsigned h;
    asm("cvt.rna.tf32.f32 %0, %1;" : "=r"(h) : "f"(x));
    hi = __uint_as_float(h);
    float r = x - hi;
    unsigned l;
    asm("cvt.rna.tf32.f32 %0, %1;" : "=r"(l) : "f"(r));
    lo = __uint_as_float(l);
}

__device__ __forceinline__ float ex2(float x)
{
    float r;
    asm("ex2.approx.f32 %0, %1;" : "=f"(r) : "f"(x));
    return r;
}

#define MMA_TF32(d, a, b)                                                     \
    asm volatile("mma.sync.aligned.m16n8k8.row.col.f32.tf32.tf32.f32 "        \
                 "{%0,%1,%2,%3}, {%4,%5,%6,%7}, {%8,%9}, {%0,%1,%2,%3};"      \
                 : "+f"(d[0]), "+f"(d[1]), "+f"(d[2]), "+f"(d[3])             \
                 : "r"(a[0]), "r"(a[1]), "r"(a[2]), "r"(a[3]),                \
                   "r"(b[0]), "r"(b[1]))

// ---------------------------------------------------------------------------
// 3xTF32 tensor-core GEMM (unchanged from R1 — known good)
// ---------------------------------------------------------------------------
#define ASTR 36
#define WSTR 136
#define GEMM_SMEM ((128 * ASTR * 2 + 32 * WSTR * 2) * 4)

__device__ __forceinline__ void gemm3x_tile(const float* __restrict__ A,
                                            const float* __restrict__ W,
                                            float* __restrict__ C,
                                            const float* __restrict__ bias,
                                            int rowBlk, int colBlk)
{
    extern __shared__ float sm[];
    float* Ah = sm;
    float* Al = Ah + 128 * ASTR;
    float* Wh = Al + 128 * ASTR;
    float* Wl = Wh + 32 * WSTR;

    const int tid  = threadIdx.x;
    const int wid  = tid >> 5, lane = tid & 31;
    const int g    = lane >> 2, t = lane & 3;
    const int wm   = (wid & 3) * 32;
    const int wn   = (wid >> 2) * 64;

    const float* Ap = A + (size_t)(rowBlk * 128) * Dq;
    const float* Wp = W + colBlk * 128;

    const int ar = tid >> 1, ac = (tid & 1) * 16;
    const int wr = tid >> 3, wc = (tid & 7) * 16;

    float acc[2][8][4] = {};

    for (int k0 = 0; k0 < Dq; k0 += 32) {
        __syncthreads();
#pragma unroll
        for (int i = 0; i < 4; i++) {
            float4 v = *(const float4*)(Ap + (size_t)ar * Dq + k0 + ac + i * 4);
            float h, l;
            split_tf32(v.x, h, l); Ah[ar * ASTR + ac + i * 4 + 0] = h; Al[ar * ASTR + ac + i * 4 + 0] = l;
            split_tf32(v.y, h, l); Ah[ar * ASTR + ac + i * 4 + 1] = h; Al[ar * ASTR + ac + i * 4 + 1] = l;
            split_tf32(v.z, h, l); Ah[ar * ASTR + ac + i * 4 + 2] = h; Al[ar * ASTR + ac + i * 4 + 2] = l;
            split_tf32(v.w, h, l); Ah[ar * ASTR + ac + i * 4 + 3] = h; Al[ar * ASTR + ac + i * 4 + 3] = l;
        }
#pragma unroll
        for (int i = 0; i < 4; i++) {
            float4 v = *(const float4*)(Wp + (size_t)(k0 + wr) * Dq + wc + i * 4);
            float h, l;
            split_tf32(v.x, h, l); Wh[wr * WSTR + wc + i * 4 + 0] = h; Wl[wr * WSTR + wc + i * 4 + 0] = l;
            split_tf32(v.y, h, l); Wh[wr * WSTR + wc + i * 4 + 1] = h; Wl[wr * WSTR + wc + i * 4 + 1] = l;
            split_tf32(v.z, h, l); Wh[wr * WSTR + wc + i * 4 + 2] = h; Wl[wr * WSTR + wc + i * 4 + 2] = l;
            split_tf32(v.w, h, l); Wh[wr * WSTR + wc + i * 4 + 3] = h; Wl[wr * WSTR + wc + i * 4 + 3] = l;
        }
        __syncthreads();

#pragma unroll
        for (int kk = 0; kk < 32; kk += 8) {
            unsigned ah[2][4], al[2][4];
#pragma unroll
            for (int mt = 0; mt < 2; mt++) {
                int r0 = wm + mt * 16 + g;
                ah[mt][0] = __float_as_uint(Ah[(r0    ) * ASTR + kk + t    ]);
                ah[mt][1] = __float_as_uint(Ah[(r0 + 8) * ASTR + kk + t    ]);
                ah[mt][2] = __float_as_uint(Ah[(r0    ) * ASTR + kk + t + 4]);
                ah[mt][3] = __float_as_uint(Ah[(r0 + 8) * ASTR + kk + t + 4]);
                al[mt][0] = __float_as_uint(Al[(r0    ) * ASTR + kk + t    ]);
                al[mt][1] = __float_as_uint(Al[(r0 + 8) * ASTR + kk + t    ]);
                al[mt][2] = __float_as_uint(Al[(r0    ) * ASTR + kk + t + 4]);
                al[mt][3] = __float_as_uint(Al[(r0 + 8) * ASTR + kk + t + 4]);
            }
            unsigned bh[8][2], bl[8][2];
#pragma unroll
            for (int nt = 0; nt < 8; nt++) {
                int c = wn + nt * 8 + g;
                bh[nt][0] = __float_as_uint(Wh[(kk + t    ) * WSTR + c]);
                bh[nt][1] = __float_as_uint(Wh[(kk + t + 4) * WSTR + c]);
                bl[nt][0] = __float_as_uint(Wl[(kk + t    ) * WSTR + c]);
                bl[nt][1] = __float_as_uint(Wl[(kk + t + 4) * WSTR + c]);
            }
#pragma unroll
            for (int mt = 0; mt < 2; mt++)
#pragma unroll
                for (int nt = 0; nt < 8; nt++) {
                    MMA_TF32(acc[mt][nt], ah[mt], bh[nt]);
                    MMA_TF32(acc[mt][nt], al[mt], bh[nt]);
                    MMA_TF32(acc[mt][nt], ah[mt], bl[nt]);
                }
        }
    }

#pragma unroll
    for (int mt = 0; mt < 2; mt++) {
        int r0 = rowBlk * 128 + wm + mt * 16 + g;
#pragma unroll
        for (int nt = 0; nt < 8; nt++) {
            int c = colBlk * 128 + wn + nt * 8 + 2 * t;
            float b0 = 0.f, b1 = 0.f;
            if (bias) { b0 = bias[c]; b1 = bias[c + 1]; }
            *(float2*)(C + (size_t)r0 * Dq + c) =
                make_float2(acc[mt][nt][0] + b0, acc[mt][nt][1] + b1);
            *(float2*)(C + (size_t)(r0 + 8) * Dq + c) =
                make_float2(acc[mt][nt][2] + b0, acc[mt][nt][3] + b1);
        }
    }
}

__global__ __launch_bounds__(256) void qkv_gemm(const float* __restrict__ x,
                                                const float* __restrict__ Wq,
                                                const float* __restrict__ Wk,
                                                const float* __restrict__ Wv)
{
    int w = blockIdx.x >> 3, colBlk = blockIdx.x & 7;
    const float* W = (w == 0) ? Wq : (w == 1) ? Wk : Wv;
    float* C       = (w == 0) ? g_q : (w == 1) ? g_k : g_v;
    gemm3x_tile(x, W, C, nullptr, blockIdx.y, colBlk);
}

__global__ __launch_bounds__(256) void out_proj(const float* __restrict__ Wo,
                                                const float* __restrict__ bo,
                                                float* __restrict__ out)
{
    gemm3x_tile(g_ao, Wo, out, bo, blockIdx.y, blockIdx.x);
}

// ---------------------------------------------------------------------------
// Tensor-core flash attention (3xTF32), ALiBi + causal.
// St = K @ Q^T, Ot = V^T @ P^T. FIX vs R2: PSTR 72 -> 136 (Pt is [64][128]).
// ---------------------------------------------------------------------------
#define QSTR 68
#define KSTR 68
#define VSTR 72
#define PSTR 136
#define FLTC_SMEM ((2 * 128 * QSTR + 2 * 64 * KSTR + 2 * 64 * VSTR + 64 * PSTR + 512) * 4)

__global__ __launch_bounds__(256, 1) void flash_alibi_tc()
{
    extern __shared__ float sm[];
    float* Qh = sm;                        // [128][68]
    float* Ql = Qh + 128 * QSTR;
    float* Kh = Ql + 128 * QSTR;           // [64][68]
    float* Kl = Kh + 64 * KSTR;
    float* Vh = Kl + 64 * KSTR;            // [64][72]
    float* Vl = Vh + 64 * VSTR;
    float* Pt = Vl + 64 * VSTR;            // [64][136] (cols 0..127 used)
    float* mp = Pt + 64 * PSTR;            // [2][128]
    float* lp = mp + 256;                  // [2][128]

    const int tid  = threadIdx.x;
    const int lane = tid & 31, wid = tid >> 5;
    const int g = lane >> 2, t = lane & 3;
    const int iw = wid & 3;                // i-warp: 32 query cols
    const int ow = wid >> 2;               // j-warp (St) / d-warp (Ot)
    const int it = (int)gridDim.x - 1 - (int)blockIdx.x;   // heavy tiles first
    const int i0 = it * 128;
    const int h  = blockIdx.y, b = blockIdx.z;
    const float slope_l2 = exp2f(-0.5f * (float)(h + 1)) * 1.44269504f;
    const float sscale   = 0.125f * 1.44269504f;

    // ---- load + split Q tile [128][64] ----
    {
        const float* Qg = g_q + ((size_t)(b * Nq + i0) * Hq + h) * DHq;
        int i = tid >> 1, d0 = (tid & 1) * 32;
#pragma unroll
        for (int ii = 0; ii < 8; ii++) {
            int d = d0 + ii * 4;
            float4 v = *(const float4*)(Qg + (size_t)i * HDq + d);
            float h0, l0, h1, l1, h2, l2, h3, l3;
            split_tf32(v.x, h0, l0); split_tf32(v.y, h1, l1);
            split_tf32(v.z, h2, l2); split_tf32(v.w, h3, l3);
            *(float4*)(Qh + i * QSTR + d) = make_float4(h0, h1, h2, h3);
            *(float4*)(Ql + i * QSTR + d) = make_float4(l0, l1, l2, l3);
        }
    }

    float acc_o[2][4][4] = {};     // Ot: [mt(d)][nt(i)][frag]
    float m_s[8], l_s[8];
#pragma unroll
    for (int k8 = 0; k8 < 8; k8++) { m_s[k8] = -1e30f; l_s[k8] = 0.f; }

    const int njt = 2 * (it + 1);
    for (int jt = 0; jt < njt; jt++) {
        const int j0 = jt * 64;
        __syncthreads();   // protect prior Pt/K/V reads

        // ---- load + split K,V tiles [64][64] ----
        {
            int jr = tid >> 2, d0 = (tid & 3) * 4;
            size_t base = ((size_t)(b * Nq + j0 + jr) * Hq + h) * DHq;
#pragma unroll
            for (int ii = 0; ii < 4; ii++) {
                int d = d0 + ii * 16;
                float4 kv = *(const float4*)(g_k + base + d);
                float h0, l0, h1, l1, h2, l2, h3, l3;
                split_tf32(kv.x, h0, l0); split_tf32(kv.y, h1, l1);
                split_tf32(kv.z, h2, l2); split_tf32(kv.w, h3, l3);
                *(float4*)(Kh + jr * KSTR + d) = make_float4(h0, h1, h2, h3);
                *(float4*)(Kl + jr * KSTR + d) = make_float4(l0, l1, l2, l3);
                float4 vv = *(const float4*)(g_v + base + d);
                split_tf32(vv.x, h0, l0); split_tf32(vv.y, h1, l1);
                split_tf32(vv.z, h2, l2); split_tf32(vv.w, h3, l3);
                *(float4*)(Vh + jr * VSTR + d) = make_float4(h0, h1, h2, h3);
                *(float4*)(Vl + jr * VSTR + d) = make_float4(l0, l1, l2, l3);
            }
        }
        __syncthreads();

        // ---- St = K @ Q^T : warp tile 32(j) x 32(i) ----
        float s[2][4][4] = {};
#pragma unroll
        for (int kt = 0; kt < 8; kt++) {
            int kk = kt * 8;
            unsigned ah[2][4], al[2][4];
#pragma unroll
            for (int mt = 0; mt < 2; mt++) {
                int r = ow * 32 + mt * 16 + g;
                ah[mt][0] = __float_as_uint(Kh[(r    ) * KSTR + kk + t    ]);
                ah[mt][1] = __float_as_uint(Kh[(r + 8) * KSTR + kk + t    ]);
                ah[mt][2] = __float_as_uint(Kh[(r    ) * KSTR + kk + t + 4]);
                ah[mt][3] = __float_as_uint(Kh[(r + 8) * KSTR + kk + t + 4]);
                al[mt][0] = __float_as_uint(Kl[(r    ) * KSTR + kk + t    ]);
                al[mt][1] = __float_as_uint(Kl[(r + 8) * KSTR + kk + t    ]);
                al[mt][2] = __float_as_uint(Kl[(r    ) * KSTR + kk + t + 4]);
                al[mt][3] = __float_as_uint(Kl[(r + 8) * KSTR + kk + t + 4]);
            }
            unsigned bh[4][2], bl[4][2];
#pragma unroll
            for (int nt = 0; nt < 4; nt++) {
                int c = iw * 32 + nt * 8 + g;
                bh[nt][0] = __float_as_uint(Qh[c * QSTR + kk + t    ]);
                bh[nt][1] = __float_as_uint(Qh[c * QSTR + kk + t + 4]);
                bl[nt][0] = __float_as_uint(Ql[c * QSTR + kk + t    ]);
                bl[nt][1] = __float_as_uint(Ql[c * QSTR + kk + t + 4]);
            }
#pragma unroll
            for (int mt = 0; mt < 2; mt++)
#pragma unroll
                for (int nt = 0; nt < 4; nt++) {
                    MMA_TF32(s[mt][nt], ah[mt], bh[nt]);
                    MMA_TF32(s[mt][nt], al[mt], bh[nt]);
                    MMA_TF32(s[mt][nt], ah[mt], bl[nt]);
                }
        }

        // ---- scale + ALiBi + causal (log2 domain), column max ----
        float colmax[8];
#pragma unroll
        for (int k8 = 0; k8 < 8; k8++) colmax[k8] = -1e30f;
#pragma unroll
        for (int mt = 0; mt < 2; mt++)
#pragma unroll
            for (int nt = 0; nt < 4; nt++)
#pragma unroll
                for (int e = 0; e < 4; e++) {
                    int jg = j0 + ow * 32 + mt * 16 + g + ((e & 2) ? 8 : 0);
                    int ig = i0 + iw * 32 + nt * 8 + 2 * t + (e & 1);
                    float v = s[mt][nt][e] * sscale + slope_l2 * (float)(ig - jg);
                    if (jg > ig) v = -1e30f;
                    s[mt][nt][e] = v;
                    int c8 = nt * 2 + (e & 1);
                    colmax[c8] = fmaxf(colmax[c8], v);
                }
#pragma unroll
        for (int k8 = 0; k8 < 8; k8++) {
            colmax[k8] = fmaxf(colmax[k8], __shfl_xor_sync(0xffffffffu, colmax[k8], 4));
            colmax[k8] = fmaxf(colmax[k8], __shfl_xor_sync(0xffffffffu, colmax[k8], 8));
            colmax[k8] = fmaxf(colmax[k8], __shfl_xor_sync(0xffffffffu, colmax[k8], 16));
        }
        if (g == 0) {
#pragma unroll
            for (int k8 = 0; k8 < 8; k8++)
                mp[ow * 128 + iw * 32 + (k8 >> 1) * 8 + 2 * t + (k8 & 1)] = colmax[k8];
        }
        __syncthreads();

        float f[8], mnew[8];
#pragma unroll
        for (int k8 = 0; k8 < 8; k8++) {
            int irel = iw * 32 + (k8 >> 1) * 8 + 2 * t + (k8 & 1);
            float mt2 = fmaxf(mp[irel], mp[128 + irel]);
            mnew[k8] = fmaxf(m_s[k8], mt2);
            f[k8] = ex2(m_s[k8] - mnew[k8]);
            m_s[k8] = mnew[k8];
        }

        // ---- P = exp2(s - m), column sums, store Pt ----
        float csum[8];
#pragma unroll
        for (int k8 = 0; k8 < 8; k8++) csum[k8] = 0.f;
#pragma unroll
        for (int mt = 0; mt < 2; mt++)
#pragma unroll
            for (int nt = 0; nt < 4; nt++)
#pragma unroll
                for (int e = 0; e < 4; e++) {
                    int c8 = nt * 2 + (e & 1);
                    float p = ex2(s[mt][nt][e] - mnew[c8]);
                    s[mt][nt][e] = p;
                    csum[c8] += p;
                }
#pragma unroll
        for (int k8 = 0; k8 < 8; k8++) {
            csum[k8] += __shfl_xor_sync(0xffffffffu, csum[k8], 4);
            csum[k8] += __shfl_xor_sync(0xffffffffu, csum[k8], 8);
            csum[k8] += __shfl_xor_sync(0xffffffffu, csum[k8], 16);
        }
        if (g == 0) {
#pragma unroll
            for (int k8 = 0; k8 < 8; k8++)
                lp[ow * 128 + iw * 32 + (k8 >> 1) * 8 + 2 * t + (k8 & 1)] = csum[k8];
        }
#pragma unroll
        for (int mt = 0; mt < 2; mt++) {
            int row = ow * 32 + mt * 16 + g;
#pragma unroll
            for (int nt = 0; nt < 4; nt++) {
                int col = iw * 32 + nt * 8 + 2 * t;
                *(float2*)(Pt + row * PSTR + col)       = make_float2(s[mt][nt][0], s[mt][nt][1]);
                *(float2*)(Pt + (row + 8) * PSTR + col) = make_float2(s[mt][nt][2], s[mt][nt][3]);
            }
        }
        __syncthreads();

        // ---- l update, rescale O ----
#pragma unroll
        for (int k8 = 0; k8 < 8; k8++) {
            int irel = iw * 32 + (k8 >> 1) * 8 + 2 * t + (k8 & 1);
            l_s[k8] = l_s[k8] * f[k8] + (lp[irel] + lp[128 + irel]);
        }
#pragma unroll
        for (int mt = 0; mt < 2; mt++)
#pragma unroll
            for (int nt = 0; nt < 4; nt++)
#pragma unroll
                for (int e = 0; e < 4; e++)
                    acc_o[mt][nt][e] *= f[nt * 2 + (e & 1)];

        // ---- Ot += V^T @ P^T : warp tile 32(d) x 32(i) ----
#pragma unroll
        for (int kt = 0; kt < 8; kt++) {
            int kk = kt * 8;
            unsigned vh_[2][4], vl_[2][4];
#pragma unroll
            for (int mt = 0; mt < 2; mt++) {
                int dc = ow * 32 + mt * 16 + g;
                vh_[mt][0] = __float_as_uint(Vh[(kk + t    ) * VSTR + dc    ]);
                vh_[mt][1] = __float_as_uint(Vh[(kk + t    ) * VSTR + dc + 8]);
                vh_[mt][2] = __float_as_uint(Vh[(kk + t + 4) * VSTR + dc    ]);
                vh_[mt][3] = __float_as_uint(Vh[(kk + t + 4) * VSTR + dc + 8]);
                vl_[mt][0] = __float_as_uint(Vl[(kk + t    ) * VSTR + dc    ]);
                vl_[mt][1] = __float_as_uint(Vl[(kk + t    ) * VSTR + dc + 8]);
                vl_[mt][2] = __float_as_uint(Vl[(kk + t + 4) * VSTR + dc    ]);
                vl_[mt][3] = __float_as_uint(Vl[(kk + t + 4) * VSTR + dc + 8]);
            }
            unsigned ph[4][2], pl[4][2];
#pragma unroll
            for (int nt = 0; nt < 4; nt++) {
                int ic = iw * 32 + nt * 8 + g;
                float p0 = Pt[(kk + t    ) * PSTR + ic];
                float p1 = Pt[(kk + t + 4) * PSTR + ic];
                float hh, ll;
                split_tf32(p0, hh, ll);
                ph[nt][0] = __float_as_uint(hh); pl[nt][0] = __float_as_uint(ll);
                split_tf32(p1, hh, ll);
                ph[nt][1] = __float_as_uint(hh); pl[nt][1] = __float_as_uint(ll);
            }
#pragma unroll
            for (int mt = 0; mt < 2; mt++)
#pragma unroll
                for (int nt = 0; nt < 4; nt++) {
                    MMA_TF32(acc_o[mt][nt], vh_[mt], ph[nt]);
                    MMA_TF32(acc_o[mt][nt], vl_[mt], ph[nt]);
                    MMA_TF32(acc_o[mt][nt], vh_[mt], pl[nt]);
                }
        }
    }

    // ---- normalize + write Ot -> g_ao[i][h][d] ----
    float inv[8];
#pragma unroll
    for (int k8 = 0; k8 < 8; k8++) inv[k8] = 1.f / l_s[k8];
#pragma unroll
    for (int mt = 0; mt < 2; mt++)
#pragma unroll
        for (int nt = 0; nt < 4; nt++)
#pragma unroll
            for (int e = 0; e < 4; e++) {
                int d  = ow * 32 + mt * 16 + g + ((e & 2) ? 8 : 0);
                int ig = i0 + iw * 32 + nt * 8 + 2 * t + (e & 1);
                g_ao[((size_t)(b * Nq + ig) * Hq + h) * DHq + d] =
                    acc_o[mt][nt][e] * inv[nt * 2 + (e & 1)];
            }
}

// ---------------------------------------------------------------------------
extern "C" void kernel_launch(void* const* d_in, const int* in_sizes, int n_in,
                              void* d_out, int out_size)
{
    (void)in_sizes; (void)n_in; (void)out_size;
    const float* x  = (const float*)d_in[0];
    const float* Wq = (const float*)d_in[1];
    const float* Wk = (const float*)d_in[2];
    const float* Wv = (const float*)d_in[3];
    const float* Wo = (const float*)d_in[4];
    const float* bo = (const float*)d_in[5];
    float* out = (float*)d_out;

    cudaFuncSetAttribute(qkv_gemm, cudaFuncAttributeMaxDynamicSharedMemorySize, GEMM_SMEM);
    cudaFuncSetAttribute(out_proj, cudaFuncAttributeMaxDynamicSharedMemorySize, GEMM_SMEM);
    cudaFuncSetAttribute(flash_alibi_tc, cudaFuncAttributeMaxDynamicSharedMemorySize, FLTC_SMEM);

    qkv_gemm<<<dim3(24, 32), 256, GEMM_SMEM>>>(x, Wq, Wk, Wv);
    flash_alibi_tc<<<dim3(16, Hq, Bq), 256, FLTC_SMEM>>>();
    out_proj<<<dim3(8, 32), 256, GEMM_SMEM>>>(Wo, bo, out);
}

// round 5
// speedup vs baseline: 1.3880x; 1.0065x over previous
#include <cuda_runtime.h>

#define Bq 2
#define Nq 2048
#define Hq 16
#define DHq 64
#define Dq 1024
#define HDq (Hq * DHq)   // 1024
#define Mq (Bq * Nq)     // 4096

// tf32 hi/lo planes
__device__ float g_xh[Mq * Dq],  g_xl[Mq * Dq];
__device__ float g_wsh[4 * Dq * Dq], g_wsl[4 * Dq * Dq];   // q,k,v,o
__device__ float g_qh[Mq * HDq], g_ql[Mq * HDq];
__device__ float g_kh[Mq * HDq], g_kl[Mq * HDq];
__device__ float g_vh[Mq * HDq], g_vl[Mq * HDq];
__device__ float g_aoh[Mq * HDq], g_aol[Mq * HDq];

// ---------------------------------------------------------------------------
// helpers
// ---------------------------------------------------------------------------
__device__ __forceinline__ void split_tf32(float x, float& hi, float& lo)
{
    unsigned h;
    asm("cvt.rna.tf32.f32 %0, %1;" : "=r"(h) : "f"(x));
    hi = __uint_as_float(h);
    float r = x - hi;
    unsigned l;
    asm("cvt.rna.tf32.f32 %0, %1;" : "=r"(l) : "f"(r));
    lo = __uint_as_float(l);
}

__device__ __forceinline__ float ex2(float x)
{
    float r;
    asm("ex2.approx.f32 %0, %1;" : "=f"(r) : "f"(x));
    return r;
}

#define MMA_TF32(d, a, b)                                                     \
    asm volatile("mma.sync.aligned.m16n8k8.row.col.f32.tf32.tf32.f32 "        \
                 "{%0,%1,%2,%3}, {%4,%5,%6,%7}, {%8,%9}, {%0,%1,%2,%3};"      \
                 : "+f"(d[0]), "+f"(d[1]), "+f"(d[2]), "+f"(d[3])             \
                 : "r"(a[0]), "r"(a[1]), "r"(a[2]), "r"(a[3]),                \
                   "r"(b[0]), "r"(b[1]))

#define CP_A16(dst, src) \
    asm volatile("cp.async.cg.shared.global [%0], [%1], 16;" :: "r"(dst), "l"(src))
#define CP_COMMIT() asm volatile("cp.async.commit_group;")
#define CP_WAIT0()  asm volatile("cp.async.wait_group 0;" ::: "memory")
#define CP_WAIT1()  asm volatile("cp.async.wait_group 1;" ::: "memory")

// ---------------------------------------------------------------------------
// split kernels
// ---------------------------------------------------------------------------
__global__ __launch_bounds__(256) void split_x(const float* __restrict__ in)
{
    int i = blockIdx.x * 256 + threadIdx.x;          // over float4
    float4 v = ((const float4*)in)[i];
    float4 h4, l4;
    split_tf32(v.x, h4.x, l4.x); split_tf32(v.y, h4.y, l4.y);
    split_tf32(v.z, h4.z, l4.z); split_tf32(v.w, h4.w, l4.w);
    ((float4*)g_xh)[i] = h4;
    ((float4*)g_xl)[i] = l4;
}

__global__ __launch_bounds__(256) void split_w(const float* __restrict__ in, int w)
{
    int i = blockIdx.x * 256 + threadIdx.x;          // over float4
    float4 v = ((const float4*)in)[i];
    float4 h4, l4;
    split_tf32(v.x, h4.x, l4.x); split_tf32(v.y, h4.y, l4.y);
    split_tf32(v.z, h4.z, l4.z); split_tf32(v.w, h4.w, l4.w);
    ((float4*)(g_wsh + (size_t)w * Dq * Dq))[i] = h4;
    ((float4*)(g_wsl + (size_t)w * Dq * Dq))[i] = l4;
}

// ---------------------------------------------------------------------------
// Pipelined 3xTF32 GEMM: BM=128 BN=128 BK=16, 2-stage cp.async, 256 thr.
// A planes padded stride 20, W planes stride 136 (both conflict-free).
// ---------------------------------------------------------------------------
#define BKp 16
#define ASTRp 20
#define WSTRp 136
#define STAGE_F (128 * ASTRp * 2 + BKp * WSTRp * 2)    // 9472 floats
#define GEMMP_SMEM (2 * STAGE_F * 4)                   // 75776 B

__device__ __forceinline__ void gemm_pipe(const float* __restrict__ Ahg,
                                          const float* __restrict__ Alg,
                                          const float* __restrict__ Whg,
                                          const float* __restrict__ Wlg,
                                          float* __restrict__ Ch,
                                          float* __restrict__ Cl,
                                          const float* __restrict__ bias,
                                          int rowBlk, int colBlk)
{
    extern __shared__ float sm[];
    const unsigned smb = (unsigned)__cvta_generic_to_shared(sm);
    const int tid = threadIdx.x;
    const int wid = tid >> 5, lane = tid & 31;
    const int g = lane >> 2, t = lane & 3;
    const int wm = (wid & 3) * 32, wn = (wid >> 2) * 64;

    const size_t arow = (size_t)rowBlk * 128;
    const int ccol = colBlk * 128;

    float acc[2][8][4] = {};

    // stage offsets (floats): Ah 0, Al 128*20, Wh 2*128*20, Wl +16*136
#define PREFETCH(st, k0)                                                          \
    {                                                                             \
        unsigned base = smb + (st) * (STAGE_F * 4);                               \
        _Pragma("unroll")                                                         \
        for (int i_ = 0; i_ < 2; i_++) {                                          \
            int idx = tid * 2 + i_;                                               \
            int r = idx >> 2, c = (idx & 3) * 4;                                  \
            CP_A16(base + (unsigned)(r * ASTRp + c) * 4,                          \
                   Ahg + (arow + r) * Dq + (k0) + c);                             \
            CP_A16(base + (unsigned)(128 * ASTRp + r * ASTRp + c) * 4,            \
                   Alg + (arow + r) * Dq + (k0) + c);                             \
        }                                                                         \
        _Pragma("unroll")                                                         \
        for (int i_ = 0; i_ < 2; i_++) {                                          \
            int idx = tid * 2 + i_;                                               \
            int r = idx >> 5, c = (idx & 31) * 4;                                 \
            CP_A16(base + (unsigned)(2 * 128 * ASTRp + r * WSTRp + c) * 4,        \
                   Whg + (size_t)((k0) + r) * Dq + ccol + c);                     \
            CP_A16(base + (unsigned)(2 * 128 * ASTRp + BKp * WSTRp + r * WSTRp + c) * 4, \
                   Wlg + (size_t)((k0) + r) * Dq + ccol + c);                     \
        }                                                                         \
    }

    PREFETCH(0, 0);
    CP_COMMIT();

    const int nch = Dq / BKp;   // 64
    for (int chn = 0; chn < nch; chn++) {
        if (chn + 1 < nch) {
            PREFETCH((chn + 1) & 1, (chn + 1) * BKp);
            CP_COMMIT();
            CP_WAIT1();
        } else {
            CP_WAIT0();
        }
        __syncthreads();

        const float* Ah = sm + (chn & 1) * STAGE_F;
        const float* Al = Ah + 128 * ASTRp;
        const float* Wh = Al + 128 * ASTRp;
        const float* Wl = Wh + BKp * WSTRp;

#pragma unroll
        for (int kk = 0; kk < BKp; kk += 8) {
            unsigned ah[2][4], al[2][4];
#pragma unroll
            for (int mt = 0; mt < 2; mt++) {
                int r0 = wm + mt * 16 + g;
                ah[mt][0] = __float_as_uint(Ah[(r0    ) * ASTRp + kk + t    ]);
                ah[mt][1] = __float_as_uint(Ah[(r0 + 8) * ASTRp + kk + t    ]);
                ah[mt][2] = __float_as_uint(Ah[(r0    ) * ASTRp + kk + t + 4]);
                ah[mt][3] = __float_as_uint(Ah[(r0 + 8) * ASTRp + kk + t + 4]);
                al[mt][0] = __float_as_uint(Al[(r0    ) * ASTRp + kk + t    ]);
                al[mt][1] = __float_as_uint(Al[(r0 + 8) * ASTRp + kk + t    ]);
                al[mt][2] = __float_as_uint(Al[(r0    ) * ASTRp + kk + t + 4]);
                al[mt][3] = __float_as_uint(Al[(r0 + 8) * ASTRp + kk + t + 4]);
            }
            unsigned bh[8][2], bl[8][2];
#pragma unroll
            for (int nt = 0; nt < 8; nt++) {
                int c = wn + nt * 8 + g;
                bh[nt][0] = __float_as_uint(Wh[(kk + t    ) * WSTRp + c]);
                bh[nt][1] = __float_as_uint(Wh[(kk + t + 4) * WSTRp + c]);
                bl[nt][0] = __float_as_uint(Wl[(kk + t    ) * WSTRp + c]);
                bl[nt][1] = __float_as_uint(Wl[(kk + t + 4) * WSTRp + c]);
            }
#pragma unroll
            for (int mt = 0; mt < 2; mt++)
#pragma unroll
                for (int nt = 0; nt < 8; nt++) {
                    MMA_TF32(acc[mt][nt], ah[mt], bh[nt]);
                    MMA_TF32(acc[mt][nt], al[mt], bh[nt]);
                    MMA_TF32(acc[mt][nt], ah[mt], bl[nt]);
                }
        }
        __syncthreads();
    }

    // epilogue: Cl != nullptr -> write split planes (no bias); else plain + bias
#pragma unroll
    for (int mt = 0; mt < 2; mt++) {
        size_t r0 = arow + wm + mt * 16 + g;
#pragma unroll
        for (int nt = 0; nt < 8; nt++) {
            int c = ccol + wn + nt * 8 + 2 * t;
            if (Cl) {
                float h0, l0, h1, l1;
                split_tf32(acc[mt][nt][0], h0, l0);
                split_tf32(acc[mt][nt][1], h1, l1);
                *(float2*)(Ch + r0 * Dq + c) = make_float2(h0, h1);
                *(float2*)(Cl + r0 * Dq + c) = make_float2(l0, l1);
                split_tf32(acc[mt][nt][2], h0, l0);
                split_tf32(acc[mt][nt][3], h1, l1);
                *(float2*)(Ch + (r0 + 8) * Dq + c) = make_float2(h0, h1);
                *(float2*)(Cl + (r0 + 8) * Dq + c) = make_float2(l0, l1);
            } else {
                float b0 = bias[c], b1 = bias[c + 1];
                *(float2*)(Ch + r0 * Dq + c) =
                    make_float2(acc[mt][nt][0] + b0, acc[mt][nt][1] + b1);
                *(float2*)(Ch + (r0 + 8) * Dq + c) =
                    make_float2(acc[mt][nt][2] + b0, acc[mt][nt][3] + b1);
            }
        }
    }
#undef PREFETCH
}

__global__ __launch_bounds__(256, 2) void qkv_gemm_p()
{
    int w = blockIdx.x >> 3, colBlk = blockIdx.x & 7;
    float* Ch = (w == 0) ? g_qh : (w == 1) ? g_kh : g_vh;
    float* Cl = (w == 0) ? g_ql : (w == 1) ? g_kl : g_vl;
    gemm_pipe(g_xh, g_xl,
              g_wsh + (size_t)w * Dq * Dq, g_wsl + (size_t)w * Dq * Dq,
              Ch, Cl, nullptr, blockIdx.y, colBlk);
}

__global__ __launch_bounds__(256, 2) void out_proj_p(const float* __restrict__ bo,
                                                     float* __restrict__ out)
{
    gemm_pipe(g_aoh, g_aol,
              g_wsh + (size_t)3 * Dq * Dq, g_wsl + (size_t)3 * Dq * Dq,
              out, nullptr, bo, blockIdx.y, blockIdx.x);
}

// ---------------------------------------------------------------------------
// Tensor-core flash attention (3xTF32), ALiBi + causal, plane inputs.
// St = K @ Q^T, Ot = V^T @ P^T.
// ---------------------------------------------------------------------------
#define QSTR 68
#define KSTR 68
#define VSTR 72
#define PSTR 136
#define OFF_QH 0
#define OFF_QL (128 * QSTR)
#define OFF_KH (2 * 128 * QSTR)
#define OFF_KL (OFF_KH + 64 * KSTR)
#define OFF_VH (OFF_KL + 64 * KSTR)
#define OFF_VL (OFF_VH + 64 * VSTR)
#define OFF_PT (OFF_VL + 64 * VSTR)
#define OFF_MP (OFF_PT + 64 * PSTR)
#define OFF_LP (OFF_MP + 256)
#define FLTC_SMEM ((OFF_LP + 256) * 4)

__global__ __launch_bounds__(256, 1) void flash_alibi_tc()
{
    extern __shared__ float sm[];
    const unsigned smb = (unsigned)__cvta_generic_to_shared(sm);
    float* Qh = sm + OFF_QH;
    float* Ql = sm + OFF_QL;
    float* Kh = sm + OFF_KH;
    float* Kl = sm + OFF_KL;
    float* Vh = sm + OFF_VH;
    float* Vl = sm + OFF_VL;
    float* Pt = sm + OFF_PT;
    float* mp = sm + OFF_MP;
    float* lp = sm + OFF_LP;

    const int tid  = threadIdx.x;
    const int lane = tid & 31, wid = tid >> 5;
    const int g = lane >> 2, t = lane & 3;
    const int iw = wid & 3;
    const int ow = wid >> 2;
    const int it = (int)gridDim.x - 1 - (int)blockIdx.x;   // heavy tiles first
    const int i0 = it * 128;
    const int h  = blockIdx.y, b = blockIdx.z;
    const float slope_l2 = exp2f(-0.5f * (float)(h + 1)) * 1.44269504f;
    const float sscale   = 0.125f * 1.44269504f;

    // ---- Q tile via cp.async (plane data, no split) ----
    {
        size_t qbase = ((size_t)(b * Nq + i0) * Hq + h) * DHq;
        int i = tid >> 1, d0 = (tid & 1) * 32;
#pragma unroll
        for (int ii = 0; ii < 8; ii++) {
            int d = d0 + ii * 4;
            CP_A16(smb + (unsigned)(OFF_QH + i * QSTR + d) * 4, g_qh + qbase + (size_t)i * HDq + d);
            CP_A16(smb + (unsigned)(OFF_QL + i * QSTR + d) * 4, g_ql + qbase + (size_t)i * HDq + d);
        }
        CP_COMMIT();
    }

    float acc_o[2][4][4] = {};
    float m_s[8], l_s[8];
#pragma unroll
    for (int k8 = 0; k8 < 8; k8++) { m_s[k8] = -1e30f; l_s[k8] = 0.f; }

    const int njt = 2 * (it + 1);
    for (int jt = 0; jt < njt; jt++) {
        const int j0 = jt * 64;
        __syncthreads();   // protect prior Pt/K/V reads

        // ---- K,V tiles via cp.async ----
        {
            int jr = tid >> 2, d0 = (tid & 3) * 4;
            size_t base = ((size_t)(b * Nq + j0 + jr) * Hq + h) * DHq;
#pragma unroll
            for (int ii = 0; ii < 4; ii++) {
                int d = d0 + ii * 16;
                CP_A16(smb + (unsigned)(OFF_KH + jr * KSTR + d) * 4, g_kh + base + d);
                CP_A16(smb + (unsigned)(OFF_KL + jr * KSTR + d) * 4, g_kl + base + d);
                CP_A16(smb + (unsigned)(OFF_VH + jr * VSTR + d) * 4, g_vh + base + d);
                CP_A16(smb + (unsigned)(OFF_VL + jr * VSTR + d) * 4, g_vl + base + d);
            }
            CP_COMMIT();
            CP_WAIT0();
        }
        __syncthreads();

        // ---- St = K @ Q^T ----
        float s[2][4][4] = {};
#pragma unroll
        for (int kt = 0; kt < 8; kt++) {
            int kk = kt * 8;
            unsigned ah[2][4], al[2][4];
#pragma unroll
            for (int mt = 0; mt < 2; mt++) {
                int r = ow * 32 + mt * 16 + g;
                ah[mt][0] = __float_as_uint(Kh[(r    ) * KSTR + kk + t    ]);
                ah[mt][1] = __float_as_uint(Kh[(r + 8) * KSTR + kk + t    ]);
                ah[mt][2] = __float_as_uint(Kh[(r    ) * KSTR + kk + t + 4]);
                ah[mt][3] = __float_as_uint(Kh[(r + 8) * KSTR + kk + t + 4]);
                al[mt][0] = __float_as_uint(Kl[(r    ) * KSTR + kk + t    ]);
                al[mt][1] = __float_as_uint(Kl[(r + 8) * KSTR + kk + t    ]);
                al[mt][2] = __float_as_uint(Kl[(r    ) * KSTR + kk + t + 4]);
                al[mt][3] = __float_as_uint(Kl[(r + 8) * KSTR + kk + t + 4]);
            }
            unsigned bh[4][2], bl[4][2];
#pragma unroll
            for (int nt = 0; nt < 4; nt++) {
                int c = iw * 32 + nt * 8 + g;
                bh[nt][0] = __float_as_uint(Qh[c * QSTR + kk + t    ]);
                bh[nt][1] = __float_as_uint(Qh[c * QSTR + kk + t + 4]);
                bl[nt][0] = __float_as_uint(Ql[c * QSTR + kk + t    ]);
                bl[nt][1] = __float_as_uint(Ql[c * QSTR + kk + t + 4]);
            }
#pragma unroll
            for (int mt = 0; mt < 2; mt++)
#pragma unroll
                for (int nt = 0; nt < 4; nt++) {
                    MMA_TF32(s[mt][nt], ah[mt], bh[nt]);
                    MMA_TF32(s[mt][nt], al[mt], bh[nt]);
                    MMA_TF32(s[mt][nt], ah[mt], bl[nt]);
                }
        }

        // ---- scale + ALiBi + causal, column max ----
        float colmax[8];
#pragma unroll
        for (int k8 = 0; k8 < 8; k8++) colmax[k8] = -1e30f;
#pragma unroll
        for (int mt = 0; mt < 2; mt++)
#pragma unroll
            for (int nt = 0; nt < 4; nt++)
#pragma unroll
                for (int e = 0; e < 4; e++) {
                    int jg = j0 + ow * 32 + mt * 16 + g + ((e & 2) ? 8 : 0);
                    int ig = i0 + iw * 32 + nt * 8 + 2 * t + (e & 1);
                    float v = s[mt][nt][e] * sscale + slope_l2 * (float)(ig - jg);
                    if (jg > ig) v = -1e30f;
                    s[mt][nt][e] = v;
                    int c8 = nt * 2 + (e & 1);
                    colmax[c8] = fmaxf(colmax[c8], v);
                }
#pragma unroll
        for (int k8 = 0; k8 < 8; k8++) {
            colmax[k8] = fmaxf(colmax[k8], __shfl_xor_sync(0xffffffffu, colmax[k8], 4));
            colmax[k8] = fmaxf(colmax[k8], __shfl_xor_sync(0xffffffffu, colmax[k8], 8));
            colmax[k8] = fmaxf(colmax[k8], __shfl_xor_sync(0xffffffffu, colmax[k8], 16));
        }
        if (g == 0) {
#pragma unroll
            for (int k8 = 0; k8 < 8; k8++)
                mp[ow * 128 + iw * 32 + (k8 >> 1) * 8 + 2 * t + (k8 & 1)] = colmax[k8];
        }
        __syncthreads();

        float f[8], mnew[8];
#pragma unroll
        for (int k8 = 0; k8 < 8; k8++) {
            int irel = iw * 32 + (k8 >> 1) * 8 + 2 * t + (k8 & 1);
            float mt2 = fmaxf(mp[irel], mp[128 + irel]);
            mnew[k8] = fmaxf(m_s[k8], mt2);
            f[k8] = ex2(m_s[k8] - mnew[k8]);
            m_s[k8] = mnew[k8];
        }

        // ---- P = exp2(s - m), column sums, store Pt ----
        float csum[8];
#pragma unroll
        for (int k8 = 0; k8 < 8; k8++) csum[k8] = 0.f;
#pragma unroll
        for (int mt = 0; mt < 2; mt++)
#pragma unroll
            for (int nt = 0; nt < 4; nt++)
#pragma unroll
                for (int e = 0; e < 4; e++) {
                    int c8 = nt * 2 + (e & 1);
                    float p = ex2(s[mt][nt][e] - mnew[c8]);
                    s[mt][nt][e] = p;
                    csum[c8] += p;
                }
#pragma unroll
        for (int k8 = 0; k8 < 8; k8++) {
            csum[k8] += __shfl_xor_sync(0xffffffffu, csum[k8], 4);
            csum[k8] += __shfl_xor_sync(0xffffffffu, csum[k8], 8);
            csum[k8] += __shfl_xor_sync(0xffffffffu, csum[k8], 16);
        }
        if (g == 0) {
#pragma unroll
            for (int k8 = 0; k8 < 8; k8++)
                lp[ow * 128 + iw * 32 + (k8 >> 1) * 8 + 2 * t + (k8 & 1)] = csum[k8];
        }
#pragma unroll
        for (int mt = 0; mt < 2; mt++) {
            int row = ow * 32 + mt * 16 + g;
#pragma unroll
            for (int nt = 0; nt < 4; nt++) {
                int col = iw * 32 + nt * 8 + 2 * t;
                *(float2*)(Pt + row * PSTR + col)       = make_float2(s[mt][nt][0], s[mt][nt][1]);
                *(float2*)(Pt + (row + 8) * PSTR + col) = make_float2(s[mt][nt][2], s[mt][nt][3]);
            }
        }
        __syncthreads();

        // ---- l update, rescale O ----
#pragma unroll
        for (int k8 = 0; k8 < 8; k8++) {
            int irel = iw * 32 + (k8 >> 1) * 8 + 2 * t + (k8 & 1);
            l_s[k8] = l_s[k8] * f[k8] + (lp[irel] + lp[128 + irel]);
        }
#pragma unroll
        for (int mt = 0; mt < 2; mt++)
#pragma unroll
            for (int nt = 0; nt < 4; nt++)
#pragma unroll
                for (int e = 0; e < 4; e++)
                    acc_o[mt][nt][e] *= f[nt * 2 + (e & 1)];

        // ---- Ot += V^T @ P^T ----
#pragma unroll
        for (int kt = 0; kt < 8; kt++) {
            int kk = kt * 8;
            unsigned vh_[2][4], vl_[2][4];
#pragma unroll
            for (int mt = 0; mt < 2; mt++) {
                int dc = ow * 32 + mt * 16 + g;
                vh_[mt][0] = __float_as_uint(Vh[(kk + t    ) * VSTR + dc    ]);
                vh_[mt][1] = __float_as_uint(Vh[(kk + t    ) * VSTR + dc + 8]);
                vh_[mt][2] = __float_as_uint(Vh[(kk + t + 4) * VSTR + dc    ]);
                vh_[mt][3] = __float_as_uint(Vh[(kk + t + 4) * VSTR + dc + 8]);
                vl_[mt][0] = __float_as_uint(Vl[(kk + t    ) * VSTR + dc    ]);
                vl_[mt][1] = __float_as_uint(Vl[(kk + t    ) * VSTR + dc + 8]);
                vl_[mt][2] = __float_as_uint(Vl[(kk + t + 4) * VSTR + dc    ]);
                vl_[mt][3] = __float_as_uint(Vl[(kk + t + 4) * VSTR + dc + 8]);
            }
            unsigned ph[4][2], pl[4][2];
#pragma unroll
            for (int nt = 0; nt < 4; nt++) {
                int ic = iw * 32 + nt * 8 + g;
                float p0 = Pt[(kk + t    ) * PSTR + ic];
                float p1 = Pt[(kk + t + 4) * PSTR + ic];
                float hh, ll;
                split_tf32(p0, hh, ll);
                ph[nt][0] = __float_as_uint(hh); pl[nt][0] = __float_as_uint(ll);
                split_tf32(p1, hh, ll);
                ph[nt][1] = __float_as_uint(hh); pl[nt][1] = __float_as_uint(ll);
            }
#pragma unroll
            for (int mt = 0; mt < 2; mt++)
#pragma unroll
                for (int nt = 0; nt < 4; nt++) {
                    MMA_TF32(acc_o[mt][nt], vh_[mt], ph[nt]);
                    MMA_TF32(acc_o[mt][nt], vl_[mt], ph[nt]);
                    MMA_TF32(acc_o[mt][nt], vh_[mt], pl[nt]);
                }
        }
    }

    // ---- normalize + write split planes ----
    float inv[8];
#pragma unroll
    for (int k8 = 0; k8 < 8; k8++) inv[k8] = 1.f / l_s[k8];
#pragma unroll
    for (int mt = 0; mt < 2; mt++)
#pragma unroll
        for (int nt = 0; nt < 4; nt++)
#pragma unroll
            for (int e = 0; e < 4; e++) {
                int d  = ow * 32 + mt * 16 + g + ((e & 2) ? 8 : 0);
                int ig = i0 + iw * 32 + nt * 8 + 2 * t + (e & 1);
                size_t idx = ((size_t)(b * Nq + ig) * Hq + h) * DHq + d;
                float hh, ll;
                split_tf32(acc_o[mt][nt][e] * inv[nt * 2 + (e & 1)], hh, ll);
                g_aoh[idx] = hh;
                g_aol[idx] = ll;
            }
}

// ---------------------------------------------------------------------------
extern "C" void kernel_launch(void* const* d_in, const int* in_sizes, int n_in,
                              void* d_out, int out_size)
{
    (void)in_sizes; (void)n_in; (void)out_size;
    const float* x  = (const float*)d_in[0];
    const float* Wq = (const float*)d_in[1];
    const float* Wk = (const float*)d_in[2];
    const float* Wv = (const float*)d_in[3];
    const float* Wo = (const float*)d_in[4];
    const float* bo = (const float*)d_in[5];
    float* out = (float*)d_out;

    cudaFuncSetAttribute(qkv_gemm_p, cudaFuncAttributeMaxDynamicSharedMemorySize, GEMMP_SMEM);
    cudaFuncSetAttribute(out_proj_p, cudaFuncAttributeMaxDynamicSharedMemorySize, GEMMP_SMEM);
    cudaFuncSetAttribute(flash_alibi_tc, cudaFuncAttributeMaxDynamicSharedMemorySize, FLTC_SMEM);

    split_x<<<Mq * Dq / 4 / 256, 256>>>(x);
    split_w<<<Dq * Dq / 4 / 256, 256>>>(Wq, 0);
    split_w<<<Dq * Dq / 4 / 256, 256>>>(Wk, 1);
    split_w<<<Dq * Dq / 4 / 256, 256>>>(Wv, 2);
    split_w<<<Dq * Dq / 4 / 256, 256>>>(Wo, 3);

    qkv_gemm_p<<<dim3(24, 32), 256, GEMMP_SMEM>>>();
    flash_alibi_tc<<<dim3(16, Hq, Bq), 256, FLTC_SMEM>>>();
    out_proj_p<<<dim3(8, 32), 256, GEMMP_SMEM>>>(bo, out);
}

// round 7
// speedup vs baseline: 1.3982x; 1.0074x over previous
#include <cuda_runtime.h>

#define Bq 2
#define Nq 2048
#define Hq 16
#define DHq 64
#define Dq 1024
#define HDq (Hq * DHq)   // 1024
#define Mq (Bq * Nq)     // 4096

// tf32 hi/lo planes
__device__ float g_xh[Mq * Dq],  g_xl[Mq * Dq];
__device__ float g_wsh[4 * Dq * Dq], g_wsl[4 * Dq * Dq];   // q,k,v,o TRANSPOSED [n][k]
__device__ float g_qh[Mq * HDq], g_ql[Mq * HDq];
__device__ float g_kh[Mq * HDq], g_kl[Mq * HDq];
__device__ float g_vh[Mq * HDq], g_vl[Mq * HDq];
__device__ float g_aoh[Mq * HDq], g_aol[Mq * HDq];

// ---------------------------------------------------------------------------
// helpers
// ---------------------------------------------------------------------------
__device__ __forceinline__ void split_tf32(float x, float& hi, float& lo)
{
    unsigned h;
    asm("cvt.rna.tf32.f32 %0, %1;" : "=r"(h) : "f"(x));
    hi = __uint_as_float(h);
    float r = x - hi;
    unsigned l;
    asm("cvt.rna.tf32.f32 %0, %1;" : "=r"(l) : "f"(r));
    lo = __uint_as_float(l);
}

__device__ __forceinline__ float ex2(float x)
{
    float r;
    asm("ex2.approx.f32 %0, %1;" : "=f"(r) : "f"(x));
    return r;
}

#define MMA_TF32(d, a, b)                                                     \
    asm volatile("mma.sync.aligned.m16n8k8.row.col.f32.tf32.tf32.f32 "        \
                 "{%0,%1,%2,%3}, {%4,%5,%6,%7}, {%8,%9}, {%0,%1,%2,%3};"      \
                 : "+f"(d[0]), "+f"(d[1]), "+f"(d[2]), "+f"(d[3])             \
                 : "r"(a[0]), "r"(a[1]), "r"(a[2]), "r"(a[3]),                \
                   "r"(b[0]), "r"(b[1]))

#define LDSM_X4(r0, r1, r2, r3, addr)                                         \
    asm volatile("ldmatrix.sync.aligned.m8n8.x4.shared.b16 {%0,%1,%2,%3}, [%4];" \
                 : "=r"(r0), "=r"(r1), "=r"(r2), "=r"(r3) : "r"(addr))

#define CP_A16(dst, src) \
    asm volatile("cp.async.cg.shared.global [%0], [%1], 16;" :: "r"(dst), "l"(src))
#define CP_COMMIT() asm volatile("cp.async.commit_group;")
#define CP_WAIT0()  asm volatile("cp.async.wait_group 0;" ::: "memory")
#define CP_WAIT1()  asm volatile("cp.async.wait_group 1;" ::: "memory")

// ---------------------------------------------------------------------------
// split kernels
// ---------------------------------------------------------------------------
__global__ __launch_bounds__(256) void split_x(const float* __restrict__ in)
{
    int i = blockIdx.x * 256 + threadIdx.x;          // over float4
    float4 v = ((const float4*)in)[i];
    float4 h4, l4;
    split_tf32(v.x, h4.x, l4.x); split_tf32(v.y, h4.y, l4.y);
    split_tf32(v.z, h4.z, l4.z); split_tf32(v.w, h4.w, l4.w);
    ((float4*)g_xh)[i] = h4;
    ((float4*)g_xl)[i] = l4;
}

// transpose + split: Wt_h/l[n][k] = split(W[k][n])
__global__ __launch_bounds__(256) void split_wT(const float* __restrict__ W, int w)
{
    int n  = blockIdx.x * 32 + (threadIdx.x & 31);
    int k0 = blockIdx.y * 64 + (threadIdx.x >> 5) * 8;
    float hb[8], lb[8];
#pragma unroll
    for (int j = 0; j < 8; j++) {
        float v = W[(size_t)(k0 + j) * Dq + n];
        split_tf32(v, hb[j], lb[j]);
    }
    float* dh = g_wsh + (size_t)w * Dq * Dq + (size_t)n * Dq + k0;
    float* dl = g_wsl + (size_t)w * Dq * Dq + (size_t)n * Dq + k0;
#pragma unroll
    for (int j = 0; j < 8; j += 4) {
        *(float4*)(dh + j) = make_float4(hb[j], hb[j + 1], hb[j + 2], hb[j + 3]);
        *(float4*)(dl + j) = make_float4(lb[j], lb[j + 1], lb[j + 2], lb[j + 3]);
    }
}

// ---------------------------------------------------------------------------
// Pipelined 3xTF32 GEMM with ldmatrix fragment loads.
// BM=128 BN=128 BK=16, 2-stage cp.async, 256 thr.
// All 4 smem tiles are [128][16] fp32 padded to stride 20 (conflict-free LDSM).
// ---------------------------------------------------------------------------
#define BKp 16
#define TSTR 20
#define PLANE_F (128 * TSTR)                    // 2560 floats per plane
#define STAGE_F (4 * PLANE_F)                   // Ah Al Wh Wl
#define GEMMP_SMEM (2 * STAGE_F * 4)            // 81920 B

__device__ __forceinline__ void gemm_pipe(const float* __restrict__ Ahg,
                                          const float* __restrict__ Alg,
                                          const float* __restrict__ Whg,   // [n][k]
                                          const float* __restrict__ Wlg,
                                          float* __restrict__ Ch,
                                          float* __restrict__ Cl,
                                          const float* __restrict__ bias,
                                          int rowBlk, int colBlk)
{
    extern __shared__ float sm[];
    const unsigned smb = (unsigned)__cvta_generic_to_shared(sm);
    const int tid = threadIdx.x;
    const int wid = tid >> 5, lane = tid & 31;
    const int g = lane >> 2, t = lane & 3;
    const int wm = (wid & 3) * 32, wn = (wid >> 2) * 64;

    const size_t arow = (size_t)rowBlk * 128;
    const int ccol = colBlk * 128;

    // ldmatrix per-lane base offsets (bytes within a plane)
    const int quad = lane >> 3, lrow = lane & 7;
    const unsigned offA = (unsigned)(((wm + (quad & 1) * 8 + lrow) * TSTR + (quad >> 1) * 4) * 4);
    const unsigned offW = (unsigned)(((wn + (quad >> 1) * 8 + lrow) * TSTR + (quad & 1) * 4) * 4);

    float acc[2][8][4] = {};

    // prefetch: each thread copies 2 float4 per tile-plane (512 float4 / plane)
#define PREFETCH(st, k0)                                                          \
    {                                                                             \
        unsigned base = smb + (st) * (STAGE_F * 4);                               \
        _Pragma("unroll")                                                         \
        for (int i_ = 0; i_ < 2; i_++) {                                          \
            int idx = tid * 2 + i_;                                               \
            int r = idx >> 2, c = (idx & 3) * 4;                                  \
            CP_A16(base + (unsigned)(r * TSTR + c) * 4,                           \
                   Ahg + (arow + r) * Dq + (k0) + c);                             \
            CP_A16(base + (unsigned)(PLANE_F + r * TSTR + c) * 4,                 \
                   Alg + (arow + r) * Dq + (k0) + c);                             \
            CP_A16(base + (unsigned)(2 * PLANE_F + r * TSTR + c) * 4,             \
                   Whg + (size_t)(ccol + r) * Dq + (k0) + c);                     \
            CP_A16(base + (unsigned)(3 * PLANE_F + r * TSTR + c) * 4,             \
                   Wlg + (size_t)(ccol + r) * Dq + (k0) + c);                     \
        }                                                                         \
    }

    PREFETCH(0, 0);
    CP_COMMIT();

    const int nch = Dq / BKp;   // 64
    for (int chn = 0; chn < nch; chn++) {
        if (chn + 1 < nch) {
            PREFETCH((chn + 1) & 1, (chn + 1) * BKp);
            CP_COMMIT();
            CP_WAIT1();
        } else {
            CP_WAIT0();
        }
        __syncthreads();

        const unsigned stg = smb + (chn & 1) * (STAGE_F * 4);

#pragma unroll
        for (int kk = 0; kk < BKp; kk += 8) {
            unsigned ah[2][4], al[2][4];
#pragma unroll
            for (int mt = 0; mt < 2; mt++) {
                unsigned ao = stg + offA + (unsigned)((mt * 16 * TSTR + kk) * 4);
                LDSM_X4(ah[mt][0], ah[mt][1], ah[mt][2], ah[mt][3], ao);
                LDSM_X4(al[mt][0], al[mt][1], al[mt][2], al[mt][3],
                        ao + PLANE_F * 4);
            }
            unsigned bh[4][4], bl[4][4];
#pragma unroll
            for (int np = 0; np < 4; np++) {
                unsigned wo = stg + 2 * PLANE_F * 4 + offW +
                              (unsigned)((np * 16 * TSTR + kk) * 4);
                LDSM_X4(bh[np][0], bh[np][1], bh[np][2], bh[np][3], wo);
                LDSM_X4(bl[np][0], bl[np][1], bl[np][2], bl[np][3],
                        wo + PLANE_F * 4);
            }
#pragma unroll
            for (int mt = 0; mt < 2; mt++)
#pragma unroll
                for (int nt = 0; nt < 8; nt++) {
                    const unsigned* bhp = &bh[nt >> 1][(nt & 1) * 2];
                    const unsigned* blp = &bl[nt >> 1][(nt & 1) * 2];
                    MMA_TF32(acc[mt][nt], ah[mt], bhp);
                    MMA_TF32(acc[mt][nt], al[mt], bhp);
                    MMA_TF32(acc[mt][nt], ah[mt], blp);
                }
        }
        __syncthreads();
    }

    // epilogue
#pragma unroll
    for (int mt = 0; mt < 2; mt++) {
        size_t r0 = arow + wm + mt * 16 + g;
#pragma unroll
        for (int nt = 0; nt < 8; nt++) {
            int c = ccol + wn + nt * 8 + 2 * t;
            if (Cl) {
                float h0, l0, h1, l1;
                split_tf32(acc[mt][nt][0], h0, l0);
                split_tf32(acc[mt][nt][1], h1, l1);
                *(float2*)(Ch + r0 * Dq + c) = make_float2(h0, h1);
                *(float2*)(Cl + r0 * Dq + c) = make_float2(l0, l1);
                split_tf32(acc[mt][nt][2], h0, l0);
                split_tf32(acc[mt][nt][3], h1, l1);
                *(float2*)(Ch + (r0 + 8) * Dq + c) = make_float2(h0, h1);
                *(float2*)(Cl + (r0 + 8) * Dq + c) = make_float2(l0, l1);
            } else {
                float b0 = bias[c], b1 = bias[c + 1];
                *(float2*)(Ch + r0 * Dq + c) =
                    make_float2(acc[mt][nt][0] + b0, acc[mt][nt][1] + b1);
                *(float2*)(Ch + (r0 + 8) * Dq + c) =
                    make_float2(acc[mt][nt][2] + b0, acc[mt][nt][3] + b1);
            }
        }
    }
#undef PREFETCH
}

__global__ __launch_bounds__(256, 2) void qkv_gemm_p()
{
    int w = blockIdx.x >> 3, colBlk = blockIdx.x & 7;
    float* Ch = (w == 0) ? g_qh : (w == 1) ? g_kh : g_vh;
    float* Cl = (w == 0) ? g_ql : (w == 1) ? g_kl : g_vl;
    gemm_pipe(g_xh, g_xl,
              g_wsh + (size_t)w * Dq * Dq, g_wsl + (size_t)w * Dq * Dq,
              Ch, Cl, nullptr, blockIdx.y, colBlk);
}

__global__ __launch_bounds__(256, 2) void out_proj_p(const float* __restrict__ bo,
                                                     float* __restrict__ out)
{
    gemm_pipe(g_aoh, g_aol,
              g_wsh + (size_t)3 * Dq * Dq, g_wsl + (size_t)3 * Dq * Dq,
              out, nullptr, bo, blockIdx.y, blockIdx.x);
}

// ---------------------------------------------------------------------------
// Tensor-core flash attention (3xTF32), ALiBi + causal — identical to R4.
// ---------------------------------------------------------------------------
#define QSTR 68
#define KSTR 68
#define VSTR 72
#define PSTR 136
#define OFF_QH 0
#define OFF_QL (128 * QSTR)
#define OFF_KH (2 * 128 * QSTR)
#define OFF_KL (OFF_KH + 64 * KSTR)
#define OFF_VH (OFF_KL + 64 * KSTR)
#define OFF_VL (OFF_VH + 64 * VSTR)
#define OFF_PT (OFF_VL + 64 * VSTR)
#define OFF_MP (OFF_PT + 64 * PSTR)
#define OFF_LP (OFF_MP + 256)
#define FLTC_SMEM ((OFF_LP + 256) * 4)

__global__ __launch_bounds__(256, 1) void flash_alibi_tc()
{
    extern __shared__ float sm[];
    const unsigned smb = (unsigned)__cvta_generic_to_shared(sm);
    float* Qh = sm + OFF_QH;
    float* Ql = sm + OFF_QL;
    float* Kh = sm + OFF_KH;
    float* Kl = sm + OFF_KL;
    float* Vh = sm + OFF_VH;
    float* Vl = sm + OFF_VL;
    float* Pt = sm + OFF_PT;
    float* mp = sm + OFF_MP;
    float* lp = sm + OFF_LP;

    const int tid  = threadIdx.x;
    const int lane = tid & 31, wid = tid >> 5;
    const int g = lane >> 2, t = lane & 3;
    const int iw = wid & 3;
    const int ow = wid >> 2;
    const int it = (int)gridDim.x - 1 - (int)blockIdx.x;
    const int i0 = it * 128;
    const int h  = blockIdx.y, b = blockIdx.z;
    const float slope_l2 = exp2f(-0.5f * (float)(h + 1)) * 1.44269504f;
    const float sscale   = 0.125f * 1.44269504f;

    {
        size_t qbase = ((size_t)(b * Nq + i0) * Hq + h) * DHq;
        int i = tid >> 1, d0 = (tid & 1) * 32;
#pragma unroll
        for (int ii = 0; ii < 8; ii++) {
            int d = d0 + ii * 4;
            CP_A16(smb + (unsigned)(OFF_QH + i * QSTR + d) * 4, g_qh + qbase + (size_t)i * HDq + d);
            CP_A16(smb + (unsigned)(OFF_QL + i * QSTR + d) * 4, g_ql + qbase + (size_t)i * HDq + d);
        }
        CP_COMMIT();
    }

    float acc_o[2][4][4] = {};
    float m_s[8], l_s[8];
#pragma unroll
    for (int k8 = 0; k8 < 8; k8++) { m_s[k8] = -1e30f; l_s[k8] = 0.f; }

    const int njt = 2 * (it + 1);
    for (int jt = 0; jt < njt; jt++) {
        const int j0 = jt * 64;
        __syncthreads();

        {
            int jr = tid >> 2, d0 = (tid & 3) * 4;
            size_t base = ((size_t)(b * Nq + j0 + jr) * Hq + h) * DHq;
#pragma unroll
            for (int ii = 0; ii < 4; ii++) {
                int d = d0 + ii * 16;
                CP_A16(smb + (unsigned)(OFF_KH + jr * KSTR + d) * 4, g_kh + base + d);
                CP_A16(smb + (unsigned)(OFF_KL + jr * KSTR + d) * 4, g_kl + base + d);
                CP_A16(smb + (unsigned)(OFF_VH + jr * VSTR + d) * 4, g_vh + base + d);
                CP_A16(smb + (unsigned)(OFF_VL + jr * VSTR + d) * 4, g_vl + base + d);
            }
            CP_COMMIT();
            CP_WAIT0();
        }
        __syncthreads();

        float s[2][4][4] = {};
#pragma unroll
        for (int kt = 0; kt < 8; kt++) {
            int kk = kt * 8;
            unsigned ah[2][4], al[2][4];
#pragma unroll
            for (int mt = 0; mt < 2; mt++) {
                int r = ow * 32 + mt * 16 + g;
                ah[mt][0] = __float_as_uint(Kh[(r    ) * KSTR + kk + t    ]);
                ah[mt][1] = __float_as_uint(Kh[(r + 8) * KSTR + kk + t    ]);
                ah[mt][2] = __float_as_uint(Kh[(r    ) * KSTR + kk + t + 4]);
                ah[mt][3] = __float_as_uint(Kh[(r + 8) * KSTR + kk + t + 4]);
                al[mt][0] = __float_as_uint(Kl[(r    ) * KSTR + kk + t    ]);
                al[mt][1] = __float_as_uint(Kl[(r + 8) * KSTR + kk + t    ]);
                al[mt][2] = __float_as_uint(Kl[(r    ) * KSTR + kk + t + 4]);
                al[mt][3] = __float_as_uint(Kl[(r + 8) * KSTR + kk + t + 4]);
            }
            unsigned bh[4][2], bl[4][2];
#pragma unroll
            for (int nt = 0; nt < 4; nt++) {
                int c = iw * 32 + nt * 8 + g;
                bh[nt][0] = __float_as_uint(Qh[c * QSTR + kk + t    ]);
                bh[nt][1] = __float_as_uint(Qh[c * QSTR + kk + t + 4]);
                bl[nt][0] = __float_as_uint(Ql[c * QSTR + kk + t    ]);
                bl[nt][1] = __float_as_uint(Ql[c * QSTR + kk + t + 4]);
            }
#pragma unroll
            for (int mt = 0; mt < 2; mt++)
#pragma unroll
                for (int nt = 0; nt < 4; nt++) {
                    MMA_TF32(s[mt][nt], ah[mt], bh[nt]);
                    MMA_TF32(s[mt][nt], al[mt], bh[nt]);
                    MMA_TF32(s[mt][nt], ah[mt], bl[nt]);
                }
        }

        float colmax[8];
#pragma unroll
        for (int k8 = 0; k8 < 8; k8++) colmax[k8] = -1e30f;
#pragma unroll
        for (int mt = 0; mt < 2; mt++)
#pragma unroll
            for (int nt = 0; nt < 4; nt++)
#pragma unroll
                for (int e = 0; e < 4; e++) {
                    int jg = j0 + ow * 32 + mt * 16 + g + ((e & 2) ? 8 : 0);
                    int ig = i0 + iw * 32 + nt * 8 + 2 * t + (e & 1);
                    float v = s[mt][nt][e] * sscale + slope_l2 * (float)(ig - jg);
                    if (jg > ig) v = -1e30f;
                    s[mt][nt][e] = v;
                    int c8 = nt * 2 + (e & 1);
                    colmax[c8] = fmaxf(colmax[c8], v);
                }
#pragma unroll
        for (int k8 = 0; k8 < 8; k8++) {
            colmax[k8] = fmaxf(colmax[k8], __shfl_xor_sync(0xffffffffu, colmax[k8], 4));
            colmax[k8] = fmaxf(colmax[k8], __shfl_xor_sync(0xffffffffu, colmax[k8], 8));
            colmax[k8] = fmaxf(colmax[k8], __shfl_xor_sync(0xffffffffu, colmax[k8], 16));
        }
        if (g == 0) {
#pragma unroll
            for (int k8 = 0; k8 < 8; k8++)
                mp[ow * 128 + iw * 32 + (k8 >> 1) * 8 + 2 * t + (k8 & 1)] = colmax[k8];
        }
        __syncthreads();

        float f[8], mnew[8];
#pragma unroll
        for (int k8 = 0; k8 < 8; k8++) {
            int irel = iw * 32 + (k8 >> 1) * 8 + 2 * t + (k8 & 1);
            float mt2 = fmaxf(mp[irel], mp[128 + irel]);
            mnew[k8] = fmaxf(m_s[k8], mt2);
            f[k8] = ex2(m_s[k8] - mnew[k8]);
            m_s[k8] = mnew[k8];
        }

        float csum[8];
#pragma unroll
        for (int k8 = 0; k8 < 8; k8++) csum[k8] = 0.f;
#pragma unroll
        for (int mt = 0; mt < 2; mt++)
#pragma unroll
            for (int nt = 0; nt < 4; nt++)
#pragma unroll
                for (int e = 0; e < 4; e++) {
                    int c8 = nt * 2 + (e & 1);
                    float p = ex2(s[mt][nt][e] - mnew[c8]);
                    s[mt][nt][e] = p;
                    csum[c8] += p;
                }
#pragma unroll
        for (int k8 = 0; k8 < 8; k8++) {
            csum[k8] += __shfl_xor_sync(0xffffffffu, csum[k8], 4);
            csum[k8] += __shfl_xor_sync(0xffffffffu, csum[k8], 8);
            csum[k8] += __shfl_xor_sync(0xffffffffu, csum[k8], 16);
        }
        if (g == 0) {
#pragma unroll
            for (int k8 = 0; k8 < 8; k8++)
                lp[ow * 128 + iw * 32 + (k8 >> 1) * 8 + 2 * t + (k8 & 1)] = csum[k8];
        }
#pragma unroll
        for (int mt = 0; mt < 2; mt++) {
            int row = ow * 32 + mt * 16 + g;
#pragma unroll
            for (int nt = 0; nt < 4; nt++) {
                int col = iw * 32 + nt * 8 + 2 * t;
                *(float2*)(Pt + row * PSTR + col)       = make_float2(s[mt][nt][0], s[mt][nt][1]);
                *(float2*)(Pt + (row + 8) * PSTR + col) = make_float2(s[mt][nt][2], s[mt][nt][3]);
            }
        }
        __syncthreads();

#pragma unroll
        for (int k8 = 0; k8 < 8; k8++) {
            int irel = iw * 32 + (k8 >> 1) * 8 + 2 * t + (k8 & 1);
            l_s[k8] = l_s[k8] * f[k8] + (lp[irel] + lp[128 + irel]);
        }
#pragma unroll
        for (int mt = 0; mt < 2; mt++)
#pragma unroll
            for (int nt = 0; nt < 4; nt++)
#pragma unroll
                for (int e = 0; e < 4; e++)
                    acc_o[mt][nt][e] *= f[nt * 2 + (e & 1)];

#pragma unroll
        for (int kt = 0; kt < 8; kt++) {
            int kk = kt * 8;
            unsigned vh_[2][4], vl_[2][4];
#pragma unroll
            for (int mt = 0; mt < 2; mt++) {
                int dc = ow * 32 + mt * 16 + g;
                vh_[mt][0] = __float_as_uint(Vh[(kk + t    ) * VSTR + dc    ]);
                vh_[mt][1] = __float_as_uint(Vh[(kk + t    ) * VSTR + dc + 8]);
                vh_[mt][2] = __float_as_uint(Vh[(kk + t + 4) * VSTR + dc    ]);
                vh_[mt][3] = __float_as_uint(Vh[(kk + t + 4) * VSTR + dc + 8]);
                vl_[mt][0] = __float_as_uint(Vl[(kk + t    ) * VSTR + dc    ]);
                vl_[mt][1] = __float_as_uint(Vl[(kk + t    ) * VSTR + dc + 8]);
                vl_[mt][2] = __float_as_uint(Vl[(kk + t + 4) * VSTR + dc    ]);
                vl_[mt][3] = __float_as_uint(Vl[(kk + t + 4) * VSTR + dc + 8]);
            }
            unsigned ph[4][2], pl[4][2];
#pragma unroll
            for (int nt = 0; nt < 4; nt++) {
                int ic = iw * 32 + nt * 8 + g;
                float p0 = Pt[(kk + t    ) * PSTR + ic];
                float p1 = Pt[(kk + t + 4) * PSTR + ic];
                float hh, ll;
                split_tf32(p0, hh, ll);
                ph[nt][0] = __float_as_uint(hh); pl[nt][0] = __float_as_uint(ll);
                split_tf32(p1, hh, ll);
                ph[nt][1] = __float_as_uint(hh); pl[nt][1] = __float_as_uint(ll);
            }
#pragma unroll
            for (int mt = 0; mt < 2; mt++)
#pragma unroll
                for (int nt = 0; nt < 4; nt++) {
                    MMA_TF32(acc_o[mt][nt], vh_[mt], ph[nt]);
                    MMA_TF32(acc_o[mt][nt], vl_[mt], ph[nt]);
                    MMA_TF32(acc_o[mt][nt], vh_[mt], pl[nt]);
                }
        }
    }

    float inv[8];
#pragma unroll
    for (int k8 = 0; k8 < 8; k8++) inv[k8] = 1.f / l_s[k8];
#pragma unroll
    for (int mt = 0; mt < 2; mt++)
#pragma unroll
        for (int nt = 0; nt < 4; nt++)
#pragma unroll
            for (int e = 0; e < 4; e++) {
                int d  = ow * 32 + mt * 16 + g + ((e & 2) ? 8 : 0);
                int ig = i0 + iw * 32 + nt * 8 + 2 * t + (e & 1);
                size_t idx = ((size_t)(b * Nq + ig) * Hq + h) * DHq + d;
                float hh, ll;
                split_tf32(acc_o[mt][nt][e] * inv[nt * 2 + (e & 1)], hh, ll);
                g_aoh[idx] = hh;
                g_aol[idx] = ll;
            }
}

// ---------------------------------------------------------------------------
extern "C" void kernel_launch(void* const* d_in, const int* in_sizes, int n_in,
                              void* d_out, int out_size)
{
    (void)in_sizes; (void)n_in; (void)out_size;
    const float* x  = (const float*)d_in[0];
    const float* Wq = (const float*)d_in[1];
    const float* Wk = (const float*)d_in[2];
    const float* Wv = (const float*)d_in[3];
    const float* Wo = (const float*)d_in[4];
    const float* bo = (const float*)d_in[5];
    float* out = (float*)d_out;

    cudaFuncSetAttribute(qkv_gemm_p, cudaFuncAttributeMaxDynamicSharedMemorySize, GEMMP_SMEM);
    cudaFuncSetAttribute(out_proj_p, cudaFuncAttributeMaxDynamicSharedMemorySize, GEMMP_SMEM);
    cudaFuncSetAttribute(flash_alibi_tc, cudaFuncAttributeMaxDynamicSharedMemorySize, FLTC_SMEM);

    split_x<<<Mq * Dq / 4 / 256, 256>>>(x);
    split_wT<<<dim3(32, 16), 256>>>(Wq, 0);
    split_wT<<<dim3(32, 16), 256>>>(Wk, 1);
    split_wT<<<dim3(32, 16), 256>>>(Wv, 2);
    split_wT<<<dim3(32, 16), 256>>>(Wo, 3);

    qkv_gemm_p<<<dim3(24, 32), 256, GEMMP_SMEM>>>();
    flash_alibi_tc<<<dim3(16, Hq, Bq), 256, FLTC_SMEM>>>();
    out_proj_p<<<dim3(8, 32), 256, GEMMP_SMEM>>>(bo, out);
}